// round 1
// baseline (speedup 1.0000x reference)
#include <cuda_runtime.h>
#include <math.h>

// Problem constants
#define NROW 4096      // N = 2*B
#define BHALF 2048
#define DK   384       // 3 modalities * 128
#define DMOD 128
#define NC   512       // classes

// Scratch (device globals — no allocation allowed)
__device__ float g_F[NROW * DK];        // normalized concat features (row-major)
__device__ float g_Cp[NC * DK];         // centroids scaled by w_m/(conc+1e-12)
__device__ float g_logits[NROW * NC];   // weighted proto logits
__device__ float g_rowsum[NROW];
__device__ float g_pos[NROW];
__device__ float g_diag[NROW];

// ---------------------------------------------------------------------------
// 0) zero accumulators + output
// ---------------------------------------------------------------------------
__global__ void zero_kernel(float* out, int out_size) {
    int i = blockIdx.x * blockDim.x + threadIdx.x;
    if (i < NROW) g_rowsum[i] = 0.0f;
    if (i < out_size) out[i] = 0.0f;
}

// ---------------------------------------------------------------------------
// 1) L2-normalize each feature row, write into concatenated layout.
//    feats[m] = concat(x_i rows [0,2048), x_j rows [2048,4096)), col block m*128.
//    One warp per (tensor, row). D=128 -> 4 floats/lane (float4).
// ---------------------------------------------------------------------------
__global__ void normalize_kernel(const float* __restrict__ st_i,
                                 const float* __restrict__ st_j,
                                 const float* __restrict__ car_i,
                                 const float* __restrict__ car_j,
                                 const float* __restrict__ pl_i,
                                 const float* __restrict__ pl_j) {
    int g = (blockIdx.x * blockDim.x + threadIdx.x) >> 5;
    int lane = threadIdx.x & 31;
    if (g >= 6 * BHALF) return;
    int t = g / BHALF;     // tensor 0..5
    int r = g % BHALF;     // row within tensor
    const float* src;
    switch (t) {
        case 0: src = st_i;  break;
        case 1: src = st_j;  break;
        case 2: src = car_i; break;
        case 3: src = car_j; break;
        case 4: src = pl_i;  break;
        default: src = pl_j; break;
    }
    int m    = t >> 1;      // modality
    int half = t & 1;       // i-half or j-half

    float4 v = *reinterpret_cast<const float4*>(&src[(size_t)r * DMOD + lane * 4]);
    float ss = v.x * v.x + v.y * v.y + v.z * v.z + v.w * v.w;
    #pragma unroll
    for (int o = 16; o; o >>= 1) ss += __shfl_xor_sync(0xffffffffu, ss, o);
    float scale = 1.0f / fmaxf(sqrtf(ss), 1e-12f);

    int grow = half * BHALF + r;
    float4 o4 = make_float4(v.x * scale, v.y * scale, v.z * scale, v.w * scale);
    *reinterpret_cast<float4*>(&g_F[(size_t)grow * DK + m * DMOD + lane * 4]) = o4;
}

// ---------------------------------------------------------------------------
// 2) Scale centroids: Cp[c, m*128+d] = cen_m[c,d] * w_m / (conc[m,c] + 1e-12)
// ---------------------------------------------------------------------------
__global__ void cent_kernel(const float* __restrict__ cst,
                            const float* __restrict__ ccar,
                            const float* __restrict__ cpl,
                            const float* __restrict__ conc) {
    int idx = blockIdx.x * blockDim.x + threadIdx.x;
    if (idx >= NC * DK) return;
    int c   = idx / DK;
    int rem = idx % DK;
    int m   = rem >> 7;
    int d   = rem & 127;
    const float* cen = (m == 0) ? cst : ((m == 1) ? ccar : cpl);
    float w = (m == 0) ? 0.4f : 0.3f;
    g_Cp[idx] = cen[c * DMOD + d] * (w / (conc[m * NC + c] + 1e-12f));
}

// ---------------------------------------------------------------------------
// 3) Fused sims GEMM: S = (wF) @ F^T over K=384, tile 128x128, BK=32,
//    256 threads, 8x8 per thread. Epilogue: e=exp(2s), accumulate row sums,
//    capture diag & positive entries.
// ---------------------------------------------------------------------------
__global__ void __launch_bounds__(256, 2) sims_kernel() {
    __shared__ float As[32][128];
    __shared__ float Bs[32][128];
    __shared__ float rs[128];

    const int row0 = blockIdx.y * 128;
    const int col0 = blockIdx.x * 128;
    const int tid  = threadIdx.x;
    const int tx   = tid & 15;   // col group
    const int ty   = tid >> 4;   // row group

    float acc[8][8];
    #pragma unroll
    for (int i = 0; i < 8; i++)
        #pragma unroll
        for (int j = 0; j < 8; j++) acc[i][j] = 0.0f;

    for (int kt = 0; kt < DK; kt += 32) {
        // 128 rows x 32 k = 1024 float4 -> 4 per thread
        #pragma unroll
        for (int l = 0; l < 4; l++) {
            int idx = tid + l * 256;
            int mrow = idx >> 3;     // 0..127
            int kq   = idx & 7;      // float4 index within 32-k chunk
            int kg   = kt + kq * 4;
            float w  = (kg < 128) ? 0.4f : 0.3f;
            float4 v = *reinterpret_cast<const float4*>(&g_F[(size_t)(row0 + mrow) * DK + kg]);
            As[kq * 4 + 0][mrow] = v.x * w;
            As[kq * 4 + 1][mrow] = v.y * w;
            As[kq * 4 + 2][mrow] = v.z * w;
            As[kq * 4 + 3][mrow] = v.w * w;
            float4 u = *reinterpret_cast<const float4*>(&g_F[(size_t)(col0 + mrow) * DK + kg]);
            Bs[kq * 4 + 0][mrow] = u.x;
            Bs[kq * 4 + 1][mrow] = u.y;
            Bs[kq * 4 + 2][mrow] = u.z;
            Bs[kq * 4 + 3][mrow] = u.w;
        }
        __syncthreads();
        #pragma unroll
        for (int kk = 0; kk < 32; kk++) {
            float a[8], b[8];
            #pragma unroll
            for (int i = 0; i < 8; i++) a[i] = As[kk][ty * 8 + i];
            #pragma unroll
            for (int j = 0; j < 8; j++) b[j] = Bs[kk][tx * 8 + j];
            #pragma unroll
            for (int i = 0; i < 8; i++)
                #pragma unroll
                for (int j = 0; j < 8; j++)
                    acc[i][j] = fmaf(a[i], b[j], acc[i][j]);
        }
        __syncthreads();
    }

    if (tid < 128) rs[tid] = 0.0f;
    __syncthreads();

    #pragma unroll
    for (int i = 0; i < 8; i++) {
        int gi = row0 + ty * 8 + i;
        int pj = (gi + BHALF) & (NROW - 1);
        float local = 0.0f;
        #pragma unroll
        for (int j = 0; j < 8; j++) {
            int gj = col0 + tx * 8 + j;
            float e = __expf(2.0f * acc[i][j]);   // 1/TEMP = 2
            local += e;
            if (gj == gi) g_diag[gi] = e;
            if (gj == pj) g_pos[gi]  = e;
        }
        atomicAdd(&rs[ty * 8 + i], local);
    }
    __syncthreads();
    if (tid < 128) atomicAdd(&g_rowsum[row0 + tid], rs[tid]);
}

// ---------------------------------------------------------------------------
// 4) Proto GEMM: logits = F @ Cp^T  (4096 x 512, K=384), same tiling.
// ---------------------------------------------------------------------------
__global__ void __launch_bounds__(256, 2) proto_kernel() {
    __shared__ float As[32][128];
    __shared__ float Bs[32][128];

    const int row0 = blockIdx.y * 128;
    const int col0 = blockIdx.x * 128;
    const int tid  = threadIdx.x;
    const int tx   = tid & 15;
    const int ty   = tid >> 4;

    float acc[8][8];
    #pragma unroll
    for (int i = 0; i < 8; i++)
        #pragma unroll
        for (int j = 0; j < 8; j++) acc[i][j] = 0.0f;

    for (int kt = 0; kt < DK; kt += 32) {
        #pragma unroll
        for (int l = 0; l < 4; l++) {
            int idx = tid + l * 256;
            int mrow = idx >> 3;
            int kq   = idx & 7;
            int kg   = kt + kq * 4;
            float4 v = *reinterpret_cast<const float4*>(&g_F[(size_t)(row0 + mrow) * DK + kg]);
            As[kq * 4 + 0][mrow] = v.x;
            As[kq * 4 + 1][mrow] = v.y;
            As[kq * 4 + 2][mrow] = v.z;
            As[kq * 4 + 3][mrow] = v.w;
            float4 u = *reinterpret_cast<const float4*>(&g_Cp[(size_t)(col0 + mrow) * DK + kg]);
            Bs[kq * 4 + 0][mrow] = u.x;
            Bs[kq * 4 + 1][mrow] = u.y;
            Bs[kq * 4 + 2][mrow] = u.z;
            Bs[kq * 4 + 3][mrow] = u.w;
        }
        __syncthreads();
        #pragma unroll
        for (int kk = 0; kk < 32; kk++) {
            float a[8], b[8];
            #pragma unroll
            for (int i = 0; i < 8; i++) a[i] = As[kk][ty * 8 + i];
            #pragma unroll
            for (int j = 0; j < 8; j++) b[j] = Bs[kk][tx * 8 + j];
            #pragma unroll
            for (int i = 0; i < 8; i++)
                #pragma unroll
                for (int j = 0; j < 8; j++)
                    acc[i][j] = fmaf(a[i], b[j], acc[i][j]);
        }
        __syncthreads();
    }

    #pragma unroll
    for (int i = 0; i < 8; i++) {
        int gi = row0 + ty * 8 + i;
        #pragma unroll
        for (int j = 0; j < 8; j++) {
            int gj = col0 + tx * 8 + j;
            g_logits[(size_t)gi * NC + gj] = acc[i][j];
        }
    }
}

// ---------------------------------------------------------------------------
// 5) Finalize: per-row logsumexp over 512 logits (one warp/row), combine with
//    contrastive terms, atomically accumulate the mean into out[0].
// ---------------------------------------------------------------------------
__global__ void finalize_kernel(const int* __restrict__ labels, float* __restrict__ out) {
    int row  = (blockIdx.x * blockDim.x + threadIdx.x) >> 5;
    int lane = threadIdx.x & 31;
    if (row >= NROW) return;
    const float* lg = &g_logits[(size_t)row * NC];

    float mx = -1e30f;
    #pragma unroll
    for (int j = lane; j < NC; j += 32) mx = fmaxf(mx, lg[j]);
    #pragma unroll
    for (int o = 16; o; o >>= 1) mx = fmaxf(mx, __shfl_xor_sync(0xffffffffu, mx, o));

    float s = 0.0f;
    #pragma unroll
    for (int j = lane; j < NC; j += 32) s += __expf(lg[j] - mx);
    #pragma unroll
    for (int o = 16; o; o >>= 1) s += __shfl_xor_sync(0xffffffffu, s, o);

    if (lane == 0) {
        float lse   = mx + logf(s);
        int   lab   = labels[row];
        float loss2 = lse - lg[lab];
        // loss1 = -log(pos / (pos + neg_sum)) with pos+neg = rowsum - diag
        float loss1 = logf((g_rowsum[row] - g_diag[row]) / g_pos[row]);
        atomicAdd(out, (loss1 + loss2) * (1.0f / NROW));
    }
}

// ---------------------------------------------------------------------------
extern "C" void kernel_launch(void* const* d_in, const int* in_sizes, int n_in,
                              void* d_out, int out_size) {
    const float* st_i  = (const float*)d_in[0];
    const float* st_j  = (const float*)d_in[1];
    const float* car_i = (const float*)d_in[2];
    const float* car_j = (const float*)d_in[3];
    const float* pl_i  = (const float*)d_in[4];
    const float* pl_j  = (const float*)d_in[5];
    const int*   lab   = (const int*)d_in[6];
    const float* cst   = (const float*)d_in[7];
    const float* ccar  = (const float*)d_in[8];
    const float* cpl   = (const float*)d_in[9];
    const float* conc  = (const float*)d_in[10];
    float* out = (float*)d_out;

    zero_kernel<<<(NROW + 255) / 256, 256>>>(out, out_size);
    normalize_kernel<<<(6 * BHALF * 32 + 255) / 256, 256>>>(st_i, st_j, car_i, car_j, pl_i, pl_j);
    cent_kernel<<<(NC * DK + 255) / 256, 256>>>(cst, ccar, cpl, conc);

    dim3 gs(NROW / 128, NROW / 128);   // 32 x 32
    sims_kernel<<<gs, 256>>>();

    dim3 gp(NC / 128, NROW / 128);     // 4 x 32
    proto_kernel<<<gp, 256>>>();

    finalize_kernel<<<(NROW * 32 + 255) / 256, 256>>>(lab, out);
}

// round 2
// speedup vs baseline: 4.6546x; 4.6546x over previous
#include <cuda_runtime.h>
#include <math.h>

// Problem constants
#define NROW 4096      // N = 2*B
#define BHALF 2048
#define DK   384       // 3 modalities * 128
#define DMOD 128
#define NC   512       // classes

// Scratch (device globals — no allocation allowed)
__device__ unsigned g_Fa[NROW * DK];    // tf32 bits of weighted normalized features (A operand)
__device__ unsigned g_Fb[NROW * DK];    // tf32 bits of normalized features (B operand)
__device__ unsigned g_Cp[NC * DK];      // tf32 bits of centroids scaled by w_m/(conc+1e-12)
__device__ float g_logits[NROW * NC];   // weighted proto logits
__device__ float g_rowsum[NROW];
__device__ float g_pos[NROW];

// ---------------------------------------------------------------------------
// helpers
// ---------------------------------------------------------------------------
__device__ __forceinline__ unsigned f2tf32(float x) {
    unsigned u;
    asm("cvt.rna.tf32.f32 %0, %1;" : "=r"(u) : "f"(x));
    return u;
}

// fast exp2 on FMA pipe: |t| < ~16, rel err ~3e-6
__device__ __forceinline__ float fexp2(float t) {
    float r = t + 12582912.0f;                      // round-to-nearest integer
    int   i = __float_as_int(r) - 0x4B400000;       // the integer
    float f = t - (r - 12582912.0f);                // f in [-0.5, 0.5]
    // 2^f Taylor deg-5 in ln2
    float p = 1.3333558e-3f;
    p = fmaf(p, f, 9.6181291e-3f);
    p = fmaf(p, f, 5.5504109e-2f);
    p = fmaf(p, f, 2.4022651e-1f);
    p = fmaf(p, f, 6.9314718e-1f);
    p = fmaf(p, f, 1.0f);
    return __int_as_float(__float_as_int(p) + (i << 23));
}

__device__ __forceinline__ void mma_tf32(float* c, const unsigned* a, const unsigned* b) {
    asm volatile(
        "mma.sync.aligned.m16n8k8.row.col.f32.tf32.tf32.f32 "
        "{%0,%1,%2,%3}, {%4,%5,%6,%7}, {%8,%9}, {%0,%1,%2,%3};"
        : "+f"(c[0]), "+f"(c[1]), "+f"(c[2]), "+f"(c[3])
        : "r"(a[0]), "r"(a[1]), "r"(a[2]), "r"(a[3]), "r"(b[0]), "r"(b[1]));
}

// ---------------------------------------------------------------------------
// 0) zero accumulators + output
// ---------------------------------------------------------------------------
__global__ void zero_kernel(float* out, int out_size) {
    int i = blockIdx.x * blockDim.x + threadIdx.x;
    if (i < NROW) g_rowsum[i] = 0.0f;
    if (i < out_size) out[i] = 0.0f;
}

// ---------------------------------------------------------------------------
// 1) L2-normalize each feature row, write tf32 bits into concatenated layout.
//    One warp per (tensor, row). D=128 -> 4 floats/lane (float4).
// ---------------------------------------------------------------------------
__global__ void normalize_kernel(const float* __restrict__ st_i,
                                 const float* __restrict__ st_j,
                                 const float* __restrict__ car_i,
                                 const float* __restrict__ car_j,
                                 const float* __restrict__ pl_i,
                                 const float* __restrict__ pl_j) {
    int g = (blockIdx.x * blockDim.x + threadIdx.x) >> 5;
    int lane = threadIdx.x & 31;
    if (g >= 6 * BHALF) return;
    int t = g / BHALF;     // tensor 0..5
    int r = g % BHALF;     // row within tensor
    const float* src;
    switch (t) {
        case 0: src = st_i;  break;
        case 1: src = st_j;  break;
        case 2: src = car_i; break;
        case 3: src = car_j; break;
        case 4: src = pl_i;  break;
        default: src = pl_j; break;
    }
    int m    = t >> 1;      // modality
    int half = t & 1;       // i-half or j-half
    float w  = (m == 0) ? 0.4f : 0.3f;

    float4 v = *reinterpret_cast<const float4*>(&src[(size_t)r * DMOD + lane * 4]);
    float ss = v.x * v.x + v.y * v.y + v.z * v.z + v.w * v.w;
    #pragma unroll
    for (int o = 16; o; o >>= 1) ss += __shfl_xor_sync(0xffffffffu, ss, o);
    float scale = 1.0f / fmaxf(sqrtf(ss), 1e-12f);
    float ws = scale * w;

    int grow = half * BHALF + r;
    size_t base = (size_t)grow * DK + m * DMOD + lane * 4;
    uint4 ub = make_uint4(f2tf32(v.x * scale), f2tf32(v.y * scale),
                          f2tf32(v.z * scale), f2tf32(v.w * scale));
    uint4 ua = make_uint4(f2tf32(v.x * ws), f2tf32(v.y * ws),
                          f2tf32(v.z * ws), f2tf32(v.w * ws));
    *reinterpret_cast<uint4*>(&g_Fb[base]) = ub;
    *reinterpret_cast<uint4*>(&g_Fa[base]) = ua;
}

// ---------------------------------------------------------------------------
// 2) Scale centroids: Cp[c, m*128+d] = cen_m[c,d] * w_m / (conc[m,c] + 1e-12)
// ---------------------------------------------------------------------------
__global__ void cent_kernel(const float* __restrict__ cst,
                            const float* __restrict__ ccar,
                            const float* __restrict__ cpl,
                            const float* __restrict__ conc) {
    int idx = blockIdx.x * blockDim.x + threadIdx.x;
    if (idx >= NC * DK) return;
    int c   = idx / DK;
    int rem = idx % DK;
    int m   = rem >> 7;
    int d   = rem & 127;
    const float* cen = (m == 0) ? cst : ((m == 1) ? ccar : cpl);
    float w = (m == 0) ? 0.4f : 0.3f;
    g_Cp[idx] = f2tf32(cen[c * DMOD + d] * (w / (conc[m * NC + c] + 1e-12f)));
}

// ---------------------------------------------------------------------------
// 3) Fused sims GEMM (TF32 tensor cores): S = (wF) @ F^T over K=384.
//    Block tile 128x128, BK=32, 8 warps as 2(m) x 4(n), warp tile 64x32,
//    mma.m16n8k8. S is symmetric: only blocks with bx >= by compute; off-diag
//    blocks also accumulate transposed (column) sums.
//    Epilogue: e = exp2(S * 2/ln2) via FMA-pipe poly, row-sum reduction,
//    positive-pair capture. Diagonal handled as the constant e^2 in finalize.
// ---------------------------------------------------------------------------
__global__ void __launch_bounds__(256, 2) sims_kernel() {
    __shared__ unsigned As[128][36];
    __shared__ unsigned Bs[128][36];
    __shared__ float rs[128];
    __shared__ float rc[128];

    const int bx = blockIdx.x, by = blockIdx.y;
    if (bx < by) return;                 // symmetry: upper triangle only
    const bool diffblk = (bx != by);

    const int row0 = by * 128;
    const int col0 = bx * 128;
    const int tid  = threadIdx.x;
    const int lane = tid & 31;
    const int w    = tid >> 5;
    const int wm   = w >> 2;             // 0..1
    const int wn   = w & 3;              // 0..3
    const int g    = lane >> 2;          // 0..7
    const int t    = lane & 3;           // 0..3

    float acc[4][4][4];
    #pragma unroll
    for (int i = 0; i < 4; i++)
        #pragma unroll
        for (int j = 0; j < 4; j++)
            #pragma unroll
            for (int r = 0; r < 4; r++) acc[i][j][r] = 0.0f;

    for (int kt = 0; kt < DK; kt += 32) {
        #pragma unroll
        for (int l = 0; l < 4; l++) {
            int idx = tid + l * 256;
            int r = idx >> 3;            // 0..127
            int q = idx & 7;             // float4 within 32-k chunk
            uint4 va = *reinterpret_cast<const uint4*>(&g_Fa[(size_t)(row0 + r) * DK + kt + q * 4]);
            As[r][q * 4 + 0] = va.x; As[r][q * 4 + 1] = va.y;
            As[r][q * 4 + 2] = va.z; As[r][q * 4 + 3] = va.w;
            uint4 vb = *reinterpret_cast<const uint4*>(&g_Fb[(size_t)(col0 + r) * DK + kt + q * 4]);
            Bs[r][q * 4 + 0] = vb.x; Bs[r][q * 4 + 1] = vb.y;
            Bs[r][q * 4 + 2] = vb.z; Bs[r][q * 4 + 3] = vb.w;
        }
        __syncthreads();
        #pragma unroll
        for (int ks = 0; ks < 32; ks += 8) {
            unsigned a[4][4], b[4][2];
            #pragma unroll
            for (int i = 0; i < 4; i++) {
                int rA = wm * 64 + i * 16;
                a[i][0] = As[rA + g    ][ks + t    ];
                a[i][1] = As[rA + g + 8][ks + t    ];
                a[i][2] = As[rA + g    ][ks + t + 4];
                a[i][3] = As[rA + g + 8][ks + t + 4];
            }
            #pragma unroll
            for (int j = 0; j < 4; j++) {
                int rB = wn * 32 + j * 8;
                b[j][0] = Bs[rB + g][ks + t    ];
                b[j][1] = Bs[rB + g][ks + t + 4];
            }
            #pragma unroll
            for (int i = 0; i < 4; i++)
                #pragma unroll
                for (int j = 0; j < 4; j++)
                    mma_tf32(acc[i][j], a[i], b[j]);
        }
        __syncthreads();
    }

    // ---- epilogue ----
    if (tid < 128) { rs[tid] = 0.0f; rc[tid] = 0.0f; }
    __syncthreads();

    const float S2 = 2.8853900817779268f;   // 2 / ln(2)  (1/TEMP = 2)
    float colsum[4][2];
    #pragma unroll
    for (int j = 0; j < 4; j++) { colsum[j][0] = 0.0f; colsum[j][1] = 0.0f; }

    #pragma unroll
    for (int i = 0; i < 4; i++) {
        #pragma unroll
        for (int h = 0; h < 2; h++) {
            int rl = wm * 64 + i * 16 + h * 8 + g;
            int gi = row0 + rl;
            int pj = (gi + BHALF) & (NROW - 1);
            float sum = 0.0f;
            #pragma unroll
            for (int j = 0; j < 4; j++) {
                float e0 = fexp2(acc[i][j][2 * h]     * S2);
                float e1 = fexp2(acc[i][j][2 * h + 1] * S2);
                sum += e0 + e1;
                colsum[j][0] += e0;
                colsum[j][1] += e1;
                int gj = col0 + wn * 32 + j * 8 + 2 * t;
                if (gj == pj)     { g_pos[gi] = e0; if (diffblk) g_pos[gj]     = e0; }
                if (gj + 1 == pj) { g_pos[gi] = e1; if (diffblk) g_pos[gj + 1] = e1; }
            }
            sum += __shfl_xor_sync(0xffffffffu, sum, 1);
            sum += __shfl_xor_sync(0xffffffffu, sum, 2);
            if (t == 0) atomicAdd(&rs[rl], sum);
        }
    }
    if (diffblk) {
        #pragma unroll
        for (int j = 0; j < 4; j++) {
            #pragma unroll
            for (int p = 0; p < 2; p++) {
                float v = colsum[j][p];
                v += __shfl_xor_sync(0xffffffffu, v, 4);
                v += __shfl_xor_sync(0xffffffffu, v, 8);
                v += __shfl_xor_sync(0xffffffffu, v, 16);
                if (g == 0) atomicAdd(&rc[wn * 32 + j * 8 + 2 * t + p], v);
            }
        }
    }
    __syncthreads();
    if (tid < 128) {
        atomicAdd(&g_rowsum[row0 + tid], rs[tid]);
        if (diffblk) atomicAdd(&g_rowsum[col0 + tid], rc[tid]);
    }
}

// ---------------------------------------------------------------------------
// 4) Proto GEMM (TF32 tensor cores): logits = F @ Cp^T (4096 x 512, K=384).
// ---------------------------------------------------------------------------
__global__ void __launch_bounds__(256, 2) proto_kernel() {
    __shared__ unsigned As[128][36];
    __shared__ unsigned Bs[128][36];

    const int row0 = blockIdx.y * 128;
    const int col0 = blockIdx.x * 128;
    const int tid  = threadIdx.x;
    const int lane = tid & 31;
    const int w    = tid >> 5;
    const int wm   = w >> 2;
    const int wn   = w & 3;
    const int g    = lane >> 2;
    const int t    = lane & 3;

    float acc[4][4][4];
    #pragma unroll
    for (int i = 0; i < 4; i++)
        #pragma unroll
        for (int j = 0; j < 4; j++)
            #pragma unroll
            for (int r = 0; r < 4; r++) acc[i][j][r] = 0.0f;

    for (int kt = 0; kt < DK; kt += 32) {
        #pragma unroll
        for (int l = 0; l < 4; l++) {
            int idx = tid + l * 256;
            int r = idx >> 3;
            int q = idx & 7;
            uint4 va = *reinterpret_cast<const uint4*>(&g_Fb[(size_t)(row0 + r) * DK + kt + q * 4]);
            As[r][q * 4 + 0] = va.x; As[r][q * 4 + 1] = va.y;
            As[r][q * 4 + 2] = va.z; As[r][q * 4 + 3] = va.w;
            uint4 vb = *reinterpret_cast<const uint4*>(&g_Cp[(size_t)(col0 + r) * DK + kt + q * 4]);
            Bs[r][q * 4 + 0] = vb.x; Bs[r][q * 4 + 1] = vb.y;
            Bs[r][q * 4 + 2] = vb.z; Bs[r][q * 4 + 3] = vb.w;
        }
        __syncthreads();
        #pragma unroll
        for (int ks = 0; ks < 32; ks += 8) {
            unsigned a[4][4], b[4][2];
            #pragma unroll
            for (int i = 0; i < 4; i++) {
                int rA = wm * 64 + i * 16;
                a[i][0] = As[rA + g    ][ks + t    ];
                a[i][1] = As[rA + g + 8][ks + t    ];
                a[i][2] = As[rA + g    ][ks + t + 4];
                a[i][3] = As[rA + g + 8][ks + t + 4];
            }
            #pragma unroll
            for (int j = 0; j < 4; j++) {
                int rB = wn * 32 + j * 8;
                b[j][0] = Bs[rB + g][ks + t    ];
                b[j][1] = Bs[rB + g][ks + t + 4];
            }
            #pragma unroll
            for (int i = 0; i < 4; i++)
                #pragma unroll
                for (int j = 0; j < 4; j++)
                    mma_tf32(acc[i][j], a[i], b[j]);
        }
        __syncthreads();
    }

    #pragma unroll
    for (int i = 0; i < 4; i++) {
        #pragma unroll
        for (int h = 0; h < 2; h++) {
            int gi = row0 + wm * 64 + i * 16 + h * 8 + g;
            #pragma unroll
            for (int j = 0; j < 4; j++) {
                int gj = col0 + wn * 32 + j * 8 + 2 * t;
                g_logits[(size_t)gi * NC + gj]     = acc[i][j][2 * h];
                g_logits[(size_t)gi * NC + gj + 1] = acc[i][j][2 * h + 1];
            }
        }
    }
}

// ---------------------------------------------------------------------------
// 5) Finalize: per-row logsumexp over 512 logits (one warp/row), combine with
//    contrastive terms, atomically accumulate the mean into out[0].
// ---------------------------------------------------------------------------
__global__ void finalize_kernel(const int* __restrict__ labels, float* __restrict__ out) {
    int row  = (blockIdx.x * blockDim.x + threadIdx.x) >> 5;
    int lane = threadIdx.x & 31;
    if (row >= NROW) return;
    const float* lg = &g_logits[(size_t)row * NC];

    float mx = -1e30f;
    #pragma unroll 4
    for (int j = lane; j < NC; j += 32) mx = fmaxf(mx, lg[j]);
    #pragma unroll
    for (int o = 16; o; o >>= 1) mx = fmaxf(mx, __shfl_xor_sync(0xffffffffu, mx, o));

    const float LOG2E = 1.4426950408889634f;
    float s = 0.0f;
    #pragma unroll 4
    for (int j = lane; j < NC; j += 32) s += fexp2((lg[j] - mx) * LOG2E);
    #pragma unroll
    for (int o = 16; o; o >>= 1) s += __shfl_xor_sync(0xffffffffu, s, o);

    if (lane == 0) {
        float lse   = mx + logf(s);
        int   lab   = labels[row];
        float loss2 = lse - lg[lab];
        // loss1 = log((rowsum - diag)/pos); diag = exp(2 * 1.0) exactly
        float loss1 = logf((g_rowsum[row] - 7.3890560989306495f) / g_pos[row]);
        atomicAdd(out, (loss1 + loss2) * (1.0f / NROW));
    }
}

// ---------------------------------------------------------------------------
extern "C" void kernel_launch(void* const* d_in, const int* in_sizes, int n_in,
                              void* d_out, int out_size) {
    const float* st_i  = (const float*)d_in[0];
    const float* st_j  = (const float*)d_in[1];
    const float* car_i = (const float*)d_in[2];
    const float* car_j = (const float*)d_in[3];
    const float* pl_i  = (const float*)d_in[4];
    const float* pl_j  = (const float*)d_in[5];
    const int*   lab   = (const int*)d_in[6];
    const float* cst   = (const float*)d_in[7];
    const float* ccar  = (const float*)d_in[8];
    const float* cpl   = (const float*)d_in[9];
    const float* conc  = (const float*)d_in[10];
    float* out = (float*)d_out;

    zero_kernel<<<(NROW + 255) / 256, 256>>>(out, out_size);
    normalize_kernel<<<(6 * BHALF * 32 + 255) / 256, 256>>>(st_i, st_j, car_i, car_j, pl_i, pl_j);
    cent_kernel<<<(NC * DK + 255) / 256, 256>>>(cst, ccar, cpl, conc);

    dim3 gs(NROW / 128, NROW / 128);   // 32 x 32, lower triangle exits early
    sims_kernel<<<gs, 256>>>();

    dim3 gp(NC / 128, NROW / 128);     // 4 x 32
    proto_kernel<<<gp, 256>>>();

    finalize_kernel<<<(NROW * 32 + 255) / 256, 256>>>(lab, out);
}

// round 4
// speedup vs baseline: 7.7000x; 1.6543x over previous
#include <cuda_runtime.h>
#include <cuda_bf16.h>
#include <math.h>
#include <stdint.h>

// Problem constants
#define NROW 4096
#define BHALF 2048
#define DK   384
#define DMOD 128
#define NC   512

// Scratch (device globals)
__device__ __nv_bfloat16 g_Fa[NROW * DK];   // weighted normalized features (A operand)
__device__ __nv_bfloat16 g_Fb[NROW * DK];   // normalized features (B operand)
__device__ __nv_bfloat16 g_Cp[NC * DK];     // centroids * w_m/(conc+1e-12)
__device__ float g_logits[NROW * NC];
__device__ float g_rowsum[NROW];
__device__ float g_pos[NROW];

// ---------------------------------------------------------------------------
// helpers
// ---------------------------------------------------------------------------
__device__ __forceinline__ uint32_t smem_u32(const void* p) {
    uint32_t a;
    asm("{ .reg .u64 t; cvta.to.shared.u64 t, %1; cvt.u32.u64 %0, t; }" : "=r"(a) : "l"(p));
    return a;
}

// fast exp2 on FMA pipe
__device__ __forceinline__ float fexp2(float t) {
    float r = t + 12582912.0f;
    int   i = __float_as_int(r) - 0x4B400000;
    float f = t - (r - 12582912.0f);
    float p = 1.3333558e-3f;
    p = fmaf(p, f, 9.6181291e-3f);
    p = fmaf(p, f, 5.5504109e-2f);
    p = fmaf(p, f, 2.4022651e-1f);
    p = fmaf(p, f, 6.9314718e-1f);
    p = fmaf(p, f, 1.0f);
    return __int_as_float(__float_as_int(p) + (i << 23));
}

__device__ __forceinline__ void mma16816(float* c, const uint32_t* a, const uint32_t* b) {
    asm volatile(
        "mma.sync.aligned.m16n8k16.row.col.f32.bf16.bf16.f32 "
        "{%0,%1,%2,%3},{%4,%5,%6,%7},{%8,%9},{%0,%1,%2,%3};"
        : "+f"(c[0]), "+f"(c[1]), "+f"(c[2]), "+f"(c[3])
        : "r"(a[0]), "r"(a[1]), "r"(a[2]), "r"(a[3]), "r"(b[0]), "r"(b[1]));
}

#define LDSM_X4(r0, r1, r2, r3, addr) \
    asm volatile("ldmatrix.sync.aligned.m8n8.x4.shared.b16 {%0,%1,%2,%3}, [%4];" \
                 : "=r"(r0), "=r"(r1), "=r"(r2), "=r"(r3) : "r"(addr))

// Packed tile layout: 128 rows x 32 bf16 (64B/row), two rows per 128B line,
// SW128 XOR swizzle -> conflict-free for both cp.async fill and ldmatrix.
__device__ __forceinline__ uint32_t sw_off(int r, int kb) {
    uint32_t L = ((uint32_t)(r >> 1) << 7) | ((uint32_t)(r & 1) << 6) | (uint32_t)kb;
    return L ^ ((L >> 3) & 0x70);
}

#define STAGE_BYTES 8192   // 128*32*2

__device__ __forceinline__ void load_stage(uint32_t dA, uint32_t dB,
                                           const __nv_bfloat16* srcA,
                                           const __nv_bfloat16* srcB,
                                           const uint32_t* dst_off,
                                           const int* src_off) {
    #pragma unroll
    for (int l = 0; l < 2; l++) {
        uint64_t ga = __cvta_generic_to_global(srcA + src_off[l]);
        uint64_t gb = __cvta_generic_to_global(srcB + src_off[l]);
        asm volatile("cp.async.cg.shared.global [%0], [%1], 16;" :: "r"(dA + dst_off[l]), "l"(ga));
        asm volatile("cp.async.cg.shared.global [%0], [%1], 16;" :: "r"(dB + dst_off[l]), "l"(gb));
    }
    asm volatile("cp.async.commit_group;" ::: "memory");
}

__device__ __forceinline__ void gemm_stage(uint32_t bA, uint32_t bB,
                                           const uint32_t offA[2][4],
                                           const uint32_t offB[2][2],
                                           float acc[4][4][4]) {
    #pragma unroll
    for (int s = 0; s < 2; s++) {
        uint32_t a[4][4], b[4][2];
        #pragma unroll
        for (int i = 0; i < 4; i++)
            LDSM_X4(a[i][0], a[i][1], a[i][2], a[i][3], bA + offA[s][i]);
        #pragma unroll
        for (int jp = 0; jp < 2; jp++)
            LDSM_X4(b[2 * jp][0], b[2 * jp][1], b[2 * jp + 1][0], b[2 * jp + 1][1],
                    bB + offB[s][jp]);
        #pragma unroll
        for (int i = 0; i < 4; i++)
            #pragma unroll
            for (int j = 0; j < 4; j++)
                mma16816(acc[i][j], a[i], b[j]);
    }
}

// ---------------------------------------------------------------------------
// 0) zero rowsum + output
// ---------------------------------------------------------------------------
__global__ void zero_kernel(float* out, int out_size) {
    int i = blockIdx.x * blockDim.x + threadIdx.x;
    if (i < NROW) g_rowsum[i] = 0.0f;
    if (i < out_size) out[i] = 0.0f;
}

// ---------------------------------------------------------------------------
// 1) L2-normalize rows -> bf16 concat layout (weighted A copy + plain B copy)
// ---------------------------------------------------------------------------
__global__ void normalize_kernel(const float* __restrict__ st_i,
                                 const float* __restrict__ st_j,
                                 const float* __restrict__ car_i,
                                 const float* __restrict__ car_j,
                                 const float* __restrict__ pl_i,
                                 const float* __restrict__ pl_j) {
    int g = (blockIdx.x * blockDim.x + threadIdx.x) >> 5;
    int lane = threadIdx.x & 31;
    if (g >= 6 * BHALF) return;
    int t = g / BHALF;
    int r = g % BHALF;
    const float* src;
    switch (t) {
        case 0: src = st_i;  break;
        case 1: src = st_j;  break;
        case 2: src = car_i; break;
        case 3: src = car_j; break;
        case 4: src = pl_i;  break;
        default: src = pl_j; break;
    }
    int m    = t >> 1;
    int half = t & 1;
    float w  = (m == 0) ? 0.4f : 0.3f;

    float4 v = *reinterpret_cast<const float4*>(&src[(size_t)r * DMOD + lane * 4]);
    float ss = v.x * v.x + v.y * v.y + v.z * v.z + v.w * v.w;
    #pragma unroll
    for (int o = 16; o; o >>= 1) ss += __shfl_xor_sync(0xffffffffu, ss, o);
    float scale = 1.0f / fmaxf(sqrtf(ss), 1e-12f);
    float ws = scale * w;

    int grow = half * BHALF + r;
    size_t base = (size_t)grow * DK + m * DMOD + lane * 4;
    __nv_bfloat162 b0 = __floats2bfloat162_rn(v.x * scale, v.y * scale);
    __nv_bfloat162 b1 = __floats2bfloat162_rn(v.z * scale, v.w * scale);
    __nv_bfloat162 a0 = __floats2bfloat162_rn(v.x * ws, v.y * ws);
    __nv_bfloat162 a1 = __floats2bfloat162_rn(v.z * ws, v.w * ws);
    *reinterpret_cast<__nv_bfloat162*>(&g_Fb[base])     = b0;
    *reinterpret_cast<__nv_bfloat162*>(&g_Fb[base + 2]) = b1;
    *reinterpret_cast<__nv_bfloat162*>(&g_Fa[base])     = a0;
    *reinterpret_cast<__nv_bfloat162*>(&g_Fa[base + 2]) = a1;
}

// ---------------------------------------------------------------------------
// 2) centroids * w_m/(conc+1e-12) -> bf16
// ---------------------------------------------------------------------------
__global__ void cent_kernel(const float* __restrict__ cst,
                            const float* __restrict__ ccar,
                            const float* __restrict__ cpl,
                            const float* __restrict__ conc) {
    int idx = blockIdx.x * blockDim.x + threadIdx.x;
    if (idx >= NC * DK) return;
    int c   = idx / DK;
    int rem = idx % DK;
    int m   = rem >> 7;
    int d   = rem & 127;
    const float* cen = (m == 0) ? cst : ((m == 1) ? ccar : cpl);
    float w = (m == 0) ? 0.4f : 0.3f;
    g_Cp[idx] = __float2bfloat16_rn(cen[c * DMOD + d] * (w / (conc[m * NC + c] + 1e-12f)));
}

// ---------------------------------------------------------------------------
// 3) sims GEMM (bf16 m16n8k16 + ldmatrix + cp.async double buffer).
//    S = (wF) @ F^T, 128x128 tiles, triangular grid (528 CTAs).
//    Epilogue: exp via FMA-pipe poly, row sums + (off-diag) col sums + pos.
// ---------------------------------------------------------------------------
__global__ void __launch_bounds__(256, 2) sims_bf16() {
    __shared__ __align__(128) __nv_bfloat16 As[2][4096];
    __shared__ __align__(128) __nv_bfloat16 Bs[2][4096];
    __shared__ float rs[128];
    __shared__ float rc[128];

    // triangular decode: enumerate (by, bx) with bx >= by
    int n = blockIdx.x;
    int by = 0;
    while (n >= 32 - by) { n -= 32 - by; by++; }
    int bx = by + n;
    const bool diffblk = (bx != by);
    const int row0 = by * 128, col0 = bx * 128;

    const int tid  = threadIdx.x;
    const int lane = tid & 31;
    const int w    = tid >> 5;
    const int wm   = w >> 2;
    const int wn   = w & 3;
    const int g    = lane >> 2;
    const int t    = lane & 3;
    const int sub  = lane >> 3;
    const int lr   = lane & 7;

    uint32_t sA = smem_u32(As), sB = smem_u32(Bs);

    uint32_t dst_off[2];
    int src_off[2];
    #pragma unroll
    for (int l = 0; l < 2; l++) {
        int v = tid + l * 256;
        int r = v >> 2, c8 = v & 3;
        dst_off[l] = sw_off(r, c8 * 16);
        src_off[l] = r * DK + c8 * 8;
    }
    uint32_t offA[2][4], offB[2][2];
    #pragma unroll
    for (int s = 0; s < 2; s++) {
        int kbA = s * 32 + (sub >> 1) * 16;
        #pragma unroll
        for (int i = 0; i < 4; i++)
            offA[s][i] = sw_off(wm * 64 + i * 16 + (sub & 1) * 8 + lr, kbA);
        int kbB = s * 32 + (sub & 1) * 16;
        #pragma unroll
        for (int jp = 0; jp < 2; jp++)
            offB[s][jp] = sw_off(wn * 32 + jp * 16 + (sub >> 1) * 8 + lr, kbB);
    }

    float acc[4][4][4];
    #pragma unroll
    for (int i = 0; i < 4; i++)
        #pragma unroll
        for (int j = 0; j < 4; j++)
            #pragma unroll
            for (int r = 0; r < 4; r++) acc[i][j][r] = 0.0f;

    const __nv_bfloat16* Abase = g_Fa + (size_t)row0 * DK;
    const __nv_bfloat16* Bbase = g_Fb + (size_t)col0 * DK;

    load_stage(sA, sB, Abase, Bbase, dst_off, src_off);
    #pragma unroll 1
    for (int it = 0; it < 12; it++) {
        if (it < 11) {
            int st = (it + 1) & 1;
            load_stage(sA + st * STAGE_BYTES, sB + st * STAGE_BYTES,
                       Abase + (it + 1) * 32, Bbase + (it + 1) * 32, dst_off, src_off);
            asm volatile("cp.async.wait_group 1;" ::: "memory");
        } else {
            asm volatile("cp.async.wait_group 0;" ::: "memory");
        }
        __syncthreads();
        gemm_stage(sA + (it & 1) * STAGE_BYTES, sB + (it & 1) * STAGE_BYTES, offA, offB, acc);
        __syncthreads();
    }

    // ---- epilogue ----
    if (tid < 128) { rs[tid] = 0.0f; rc[tid] = 0.0f; }
    __syncthreads();

    const float S2 = 2.8853900817779268f;   // 2/ln2 (1/TEMP = 2)
    float colsum[4][2];
    #pragma unroll
    for (int j = 0; j < 4; j++) { colsum[j][0] = 0.0f; colsum[j][1] = 0.0f; }

    #pragma unroll
    for (int i = 0; i < 4; i++) {
        #pragma unroll
        for (int h = 0; h < 2; h++) {
            int rl = wm * 64 + i * 16 + h * 8 + g;
            int gi = row0 + rl;
            int pj = (gi + BHALF) & (NROW - 1);
            float sum = 0.0f;
            #pragma unroll
            for (int j = 0; j < 4; j++) {
                float e0 = fexp2(acc[i][j][2 * h]     * S2);
                float e1 = fexp2(acc[i][j][2 * h + 1] * S2);
                sum += e0 + e1;
                colsum[j][0] += e0;
                colsum[j][1] += e1;
                int gj = col0 + wn * 32 + j * 8 + 2 * t;
                if (gj == pj)     { g_pos[gi] = e0; if (diffblk) g_pos[gj]     = e0; }
                if (gj + 1 == pj) { g_pos[gi] = e1; if (diffblk) g_pos[gj + 1] = e1; }
            }
            sum += __shfl_xor_sync(0xffffffffu, sum, 1);
            sum += __shfl_xor_sync(0xffffffffu, sum, 2);
            if (t == 0) atomicAdd(&rs[rl], sum);
        }
    }
    if (diffblk) {
        #pragma unroll
        for (int j = 0; j < 4; j++) {
            #pragma unroll
            for (int p = 0; p < 2; p++) {
                float v = colsum[j][p];
                v += __shfl_xor_sync(0xffffffffu, v, 4);
                v += __shfl_xor_sync(0xffffffffu, v, 8);
                v += __shfl_xor_sync(0xffffffffu, v, 16);
                if (g == 0) atomicAdd(&rc[wn * 32 + j * 8 + 2 * t + p], v);
            }
        }
    }
    __syncthreads();
    if (tid < 128) {
        atomicAdd(&g_rowsum[row0 + tid], rs[tid]);
        if (diffblk) atomicAdd(&g_rowsum[col0 + tid], rc[tid]);
    }
}

// ---------------------------------------------------------------------------
// 4) proto GEMM: logits = F @ Cp^T  (4096 x 512, K=384), same engine.
// ---------------------------------------------------------------------------
__global__ void __launch_bounds__(256, 2) proto_bf16() {
    __shared__ __align__(128) __nv_bfloat16 As[2][4096];
    __shared__ __align__(128) __nv_bfloat16 Bs[2][4096];

    const int row0 = blockIdx.y * 128;
    const int col0 = blockIdx.x * 128;
    const int tid  = threadIdx.x;
    const int lane = tid & 31;
    const int w    = tid >> 5;
    const int wm   = w >> 2;
    const int wn   = w & 3;
    const int g    = lane >> 2;
    const int t    = lane & 3;
    const int sub  = lane >> 3;
    const int lr   = lane & 7;

    uint32_t sA = smem_u32(As), sB = smem_u32(Bs);

    uint32_t dst_off[2];
    int src_off[2];
    #pragma unroll
    for (int l = 0; l < 2; l++) {
        int v = tid + l * 256;
        int r = v >> 2, c8 = v & 3;
        dst_off[l] = sw_off(r, c8 * 16);
        src_off[l] = r * DK + c8 * 8;
    }
    uint32_t offA[2][4], offB[2][2];
    #pragma unroll
    for (int s = 0; s < 2; s++) {
        int kbA = s * 32 + (sub >> 1) * 16;
        #pragma unroll
        for (int i = 0; i < 4; i++)
            offA[s][i] = sw_off(wm * 64 + i * 16 + (sub & 1) * 8 + lr, kbA);
        int kbB = s * 32 + (sub & 1) * 16;
        #pragma unroll
        for (int jp = 0; jp < 2; jp++)
            offB[s][jp] = sw_off(wn * 32 + jp * 16 + (sub >> 1) * 8 + lr, kbB);
    }

    float acc[4][4][4];
    #pragma unroll
    for (int i = 0; i < 4; i++)
        #pragma unroll
        for (int j = 0; j < 4; j++)
            #pragma unroll
            for (int r = 0; r < 4; r++) acc[i][j][r] = 0.0f;

    const __nv_bfloat16* Abase = g_Fb + (size_t)row0 * DK;
    const __nv_bfloat16* Bbase = g_Cp + (size_t)col0 * DK;

    load_stage(sA, sB, Abase, Bbase, dst_off, src_off);
    #pragma unroll 1
    for (int it = 0; it < 12; it++) {
        if (it < 11) {
            int st = (it + 1) & 1;
            load_stage(sA + st * STAGE_BYTES, sB + st * STAGE_BYTES,
                       Abase + (it + 1) * 32, Bbase + (it + 1) * 32, dst_off, src_off);
            asm volatile("cp.async.wait_group 1;" ::: "memory");
        } else {
            asm volatile("cp.async.wait_group 0;" ::: "memory");
        }
        __syncthreads();
        gemm_stage(sA + (it & 1) * STAGE_BYTES, sB + (it & 1) * STAGE_BYTES, offA, offB, acc);
        __syncthreads();
    }

    #pragma unroll
    for (int i = 0; i < 4; i++) {
        #pragma unroll
        for (int h = 0; h < 2; h++) {
            int gi = row0 + wm * 64 + i * 16 + h * 8 + g;
            #pragma unroll
            for (int j = 0; j < 4; j++) {
                int gj = col0 + wn * 32 + j * 8 + 2 * t;
                g_logits[(size_t)gi * NC + gj]     = acc[i][j][2 * h];
                g_logits[(size_t)gi * NC + gj + 1] = acc[i][j][2 * h + 1];
            }
        }
    }
}

// ---------------------------------------------------------------------------
// 5) Finalize: per-row logsumexp over 512 logits + contrastive terms -> mean
// ---------------------------------------------------------------------------
__global__ void finalize_kernel(const int* __restrict__ labels, float* __restrict__ out) {
    int row  = (blockIdx.x * blockDim.x + threadIdx.x) >> 5;
    int lane = threadIdx.x & 31;
    if (row >= NROW) return;
    const float* lg = &g_logits[(size_t)row * NC];

    float mx = -1e30f;
    #pragma unroll 4
    for (int j = lane; j < NC; j += 32) mx = fmaxf(mx, lg[j]);
    #pragma unroll
    for (int o = 16; o; o >>= 1) mx = fmaxf(mx, __shfl_xor_sync(0xffffffffu, mx, o));

    const float LOG2E = 1.4426950408889634f;
    float s = 0.0f;
    #pragma unroll 4
    for (int j = lane; j < NC; j += 32) s += fexp2((lg[j] - mx) * LOG2E);
    #pragma unroll
    for (int o = 16; o; o >>= 1) s += __shfl_xor_sync(0xffffffffu, s, o);

    if (lane == 0) {
        float lse   = mx + logf(s);
        int   lab   = labels[row];
        float loss2 = lse - lg[lab];
        float loss1 = logf((g_rowsum[row] - 7.3890560989306495f) / g_pos[row]); // diag=e^2
        atomicAdd(out, (loss1 + loss2) * (1.0f / NROW));
    }
}

// ---------------------------------------------------------------------------
extern "C" void kernel_launch(void* const* d_in, const int* in_sizes, int n_in,
                              void* d_out, int out_size) {
    const float* st_i  = (const float*)d_in[0];
    const float* st_j  = (const float*)d_in[1];
    const float* car_i = (const float*)d_in[2];
    const float* car_j = (const float*)d_in[3];
    const float* pl_i  = (const float*)d_in[4];
    const float* pl_j  = (const float*)d_in[5];
    const int*   lab   = (const int*)d_in[6];
    const float* cst   = (const float*)d_in[7];
    const float* ccar  = (const float*)d_in[8];
    const float* cpl   = (const float*)d_in[9];
    const float* conc  = (const float*)d_in[10];
    float* out = (float*)d_out;

    zero_kernel<<<(NROW + 255) / 256, 256>>>(out, out_size);
    normalize_kernel<<<(6 * BHALF * 32 + 255) / 256, 256>>>(st_i, st_j, car_i, car_j, pl_i, pl_j);
    cent_kernel<<<(NC * DK + 255) / 256, 256>>>(cst, ccar, cpl, conc);

    sims_bf16<<<528, 256>>>();                 // triangular grid

    dim3 gp(NC / 128, NROW / 128);             // 4 x 32
    proto_bf16<<<gp, 256>>>();

    finalize_kernel<<<(NROW * 32 + 255) / 256, 256>>>(lab, out);
}

// round 5
// speedup vs baseline: 7.7755x; 1.0098x over previous
#include <cuda_runtime.h>
#include <cuda_bf16.h>
#include <math.h>
#include <stdint.h>

// Problem constants
#define NROW 4096
#define BHALF 2048
#define DK   384
#define DMOD 128
#define NC   512

// Scratch (device globals)
__device__ __nv_bfloat16 g_Fa[NROW * DK];   // weighted normalized features (A operand)
__device__ __nv_bfloat16 g_Fb[NROW * DK];   // normalized features (B operand)
__device__ __nv_bfloat16 g_Cp[NC * DK];     // centroids * w_m/(conc+1e-12)
__device__ float g_logits[NROW * NC];
__device__ float g_rowsum[NROW];
__device__ float g_pos[NROW];

// ---------------------------------------------------------------------------
// helpers
// ---------------------------------------------------------------------------
__device__ __forceinline__ uint32_t smem_u32(const void* p) {
    uint32_t a;
    asm("{ .reg .u64 t; cvta.to.shared.u64 t, %1; cvt.u32.u64 %0, t; }" : "=r"(a) : "l"(p));
    return a;
}

// fast exp2 on FMA pipe
__device__ __forceinline__ float fexp2(float t) {
    float r = t + 12582912.0f;
    int   i = __float_as_int(r) - 0x4B400000;
    float f = t - (r - 12582912.0f);
    float p = 1.3333558e-3f;
    p = fmaf(p, f, 9.6181291e-3f);
    p = fmaf(p, f, 5.5504109e-2f);
    p = fmaf(p, f, 2.4022651e-1f);
    p = fmaf(p, f, 6.9314718e-1f);
    p = fmaf(p, f, 1.0f);
    return __int_as_float(__float_as_int(p) + (i << 23));
}

__device__ __forceinline__ void mma16816(float* c, const uint32_t* a, const uint32_t* b) {
    asm volatile(
        "mma.sync.aligned.m16n8k16.row.col.f32.bf16.bf16.f32 "
        "{%0,%1,%2,%3},{%4,%5,%6,%7},{%8,%9},{%0,%1,%2,%3};"
        : "+f"(c[0]), "+f"(c[1]), "+f"(c[2]), "+f"(c[3])
        : "r"(a[0]), "r"(a[1]), "r"(a[2]), "r"(a[3]), "r"(b[0]), "r"(b[1]));
}

#define LDSM_X4(r0, r1, r2, r3, addr) \
    asm volatile("ldmatrix.sync.aligned.m8n8.x4.shared.b16 {%0,%1,%2,%3}, [%4];" \
                 : "=r"(r0), "=r"(r1), "=r"(r2), "=r"(r3) : "r"(addr))

// Packed tile layout: 128 rows x 32 bf16 (64B/row), two rows per 128B line,
// SW128 XOR swizzle -> conflict-free for both cp.async fill and ldmatrix.
__device__ __forceinline__ uint32_t sw_off(int r, int kb) {
    uint32_t L = ((uint32_t)(r >> 1) << 7) | ((uint32_t)(r & 1) << 6) | (uint32_t)kb;
    return L ^ ((L >> 3) & 0x70);
}

#define STAGE_BYTES 8192   // 128*32*2
#define KTILES 12          // 384 / 32

__device__ __forceinline__ void load_stage(uint32_t dA, uint32_t dB,
                                           const __nv_bfloat16* srcA,
                                           const __nv_bfloat16* srcB,
                                           const uint32_t* dst_off,
                                           const int* src_off) {
    #pragma unroll
    for (int l = 0; l < 2; l++) {
        uint64_t ga = __cvta_generic_to_global(srcA + src_off[l]);
        uint64_t gb = __cvta_generic_to_global(srcB + src_off[l]);
        asm volatile("cp.async.cg.shared.global [%0], [%1], 16;" :: "r"(dA + dst_off[l]), "l"(ga));
        asm volatile("cp.async.cg.shared.global [%0], [%1], 16;" :: "r"(dB + dst_off[l]), "l"(gb));
    }
    asm volatile("cp.async.commit_group;" ::: "memory");
}

__device__ __forceinline__ void gemm_stage(uint32_t bA, uint32_t bB,
                                           const uint32_t offA[2][4],
                                           const uint32_t offB[2][2],
                                           float acc[4][4][4]) {
    #pragma unroll
    for (int s = 0; s < 2; s++) {
        uint32_t a[4][4], b[4][2];
        #pragma unroll
        for (int i = 0; i < 4; i++)
            LDSM_X4(a[i][0], a[i][1], a[i][2], a[i][3], bA + offA[s][i]);
        #pragma unroll
        for (int jp = 0; jp < 2; jp++)
            LDSM_X4(b[2 * jp][0], b[2 * jp][1], b[2 * jp + 1][0], b[2 * jp + 1][1],
                    bB + offB[s][jp]);
        #pragma unroll
        for (int i = 0; i < 4; i++)
            #pragma unroll
            for (int j = 0; j < 4; j++)
                mma16816(acc[i][j], a[i], b[j]);
    }
}

// 3-stage mainloop: ONE barrier per iteration; writes to stage (it+2)%3 are
// safe because the barrier at top of iteration it proves all warps finished
// iteration it-1 (which last read that buffer).
#define MAINLOOP(Abase, Bbase, sA, sB)                                          \
    load_stage(sA, sB, Abase, Bbase, dst_off, src_off);                         \
    load_stage(sA + STAGE_BYTES, sB + STAGE_BYTES,                              \
               Abase + 32, Bbase + 32, dst_off, src_off);                       \
    _Pragma("unroll 1")                                                         \
    for (int it = 0; it < KTILES; it++) {                                       \
        if (it < KTILES - 1) asm volatile("cp.async.wait_group 1;" ::: "memory");\
        else                 asm volatile("cp.async.wait_group 0;" ::: "memory");\
        __syncthreads();                                                        \
        if (it + 2 < KTILES) {                                                  \
            int st = (it + 2) % 3;                                              \
            load_stage(sA + st * STAGE_BYTES, sB + st * STAGE_BYTES,            \
                       Abase + (it + 2) * 32, Bbase + (it + 2) * 32,            \
                       dst_off, src_off);                                       \
        }                                                                       \
        int cs = it % 3;                                                        \
        gemm_stage(sA + cs * STAGE_BYTES, sB + cs * STAGE_BYTES, offA, offB, acc);\
    }                                                                           \
    __syncthreads();

// ---------------------------------------------------------------------------
// 1) L2-normalize rows -> bf16 concat layout (weighted A copy + plain B copy)
// ---------------------------------------------------------------------------
__global__ void normalize_kernel(const float* __restrict__ st_i,
                                 const float* __restrict__ st_j,
                                 const float* __restrict__ car_i,
                                 const float* __restrict__ car_j,
                                 const float* __restrict__ pl_i,
                                 const float* __restrict__ pl_j) {
    int g = (blockIdx.x * blockDim.x + threadIdx.x) >> 5;
    int lane = threadIdx.x & 31;
    if (g >= 6 * BHALF) return;
    int t = g / BHALF;
    int r = g % BHALF;
    const float* src;
    switch (t) {
        case 0: src = st_i;  break;
        case 1: src = st_j;  break;
        case 2: src = car_i; break;
        case 3: src = car_j; break;
        case 4: src = pl_i;  break;
        default: src = pl_j; break;
    }
    int m    = t >> 1;
    int half = t & 1;
    float w  = (m == 0) ? 0.4f : 0.3f;

    float4 v = *reinterpret_cast<const float4*>(&src[(size_t)r * DMOD + lane * 4]);
    float ss = v.x * v.x + v.y * v.y + v.z * v.z + v.w * v.w;
    #pragma unroll
    for (int o = 16; o; o >>= 1) ss += __shfl_xor_sync(0xffffffffu, ss, o);
    float scale = 1.0f / fmaxf(sqrtf(ss), 1e-12f);
    float ws = scale * w;

    int grow = half * BHALF + r;
    size_t base = (size_t)grow * DK + m * DMOD + lane * 4;
    __nv_bfloat162 b0 = __floats2bfloat162_rn(v.x * scale, v.y * scale);
    __nv_bfloat162 b1 = __floats2bfloat162_rn(v.z * scale, v.w * scale);
    __nv_bfloat162 a0 = __floats2bfloat162_rn(v.x * ws, v.y * ws);
    __nv_bfloat162 a1 = __floats2bfloat162_rn(v.z * ws, v.w * ws);
    *reinterpret_cast<__nv_bfloat162*>(&g_Fb[base])     = b0;
    *reinterpret_cast<__nv_bfloat162*>(&g_Fb[base + 2]) = b1;
    *reinterpret_cast<__nv_bfloat162*>(&g_Fa[base])     = a0;
    *reinterpret_cast<__nv_bfloat162*>(&g_Fa[base + 2]) = a1;
}

// ---------------------------------------------------------------------------
// 2) centroids * w_m/(conc+1e-12) -> bf16; also zeros rowsum + out
// ---------------------------------------------------------------------------
__global__ void cent_kernel(const float* __restrict__ cst,
                            const float* __restrict__ ccar,
                            const float* __restrict__ cpl,
                            const float* __restrict__ conc,
                            float* __restrict__ out, int out_size) {
    int idx = blockIdx.x * blockDim.x + threadIdx.x;
    if (idx < NROW) g_rowsum[idx] = 0.0f;
    if (idx < out_size) out[idx] = 0.0f;
    if (idx >= NC * DK) return;
    int c   = idx / DK;
    int rem = idx % DK;
    int m   = rem >> 7;
    int d   = rem & 127;
    const float* cen = (m == 0) ? cst : ((m == 1) ? ccar : cpl);
    float w = (m == 0) ? 0.4f : 0.3f;
    g_Cp[idx] = __float2bfloat16_rn(cen[c * DMOD + d] * (w / (conc[m * NC + c] + 1e-12f)));
}

// ---------------------------------------------------------------------------
// 3) sims GEMM: S = (wF) @ F^T, 128x128 tiles, triangular grid (528 CTAs),
//    bf16 m16n8k16 + ldmatrix + 3-stage cp.async, 1 barrier/iter.
// ---------------------------------------------------------------------------
__global__ void __launch_bounds__(256, 2) sims_bf16() {
    __shared__ __align__(128) __nv_bfloat16 As[3][4096];
    __shared__ __align__(128) __nv_bfloat16 Bs[3][4096];

    // triangular decode: enumerate (by, bx) with bx >= by
    int n = blockIdx.x;
    int by = 0;
    while (n >= 32 - by) { n -= 32 - by; by++; }
    int bx = by + n;
    const bool diffblk = (bx != by);
    const int row0 = by * 128, col0 = bx * 128;

    const int tid  = threadIdx.x;
    const int lane = tid & 31;
    const int w    = tid >> 5;
    const int wm   = w >> 2;
    const int wn   = w & 3;
    const int g    = lane >> 2;
    const int t    = lane & 3;
    const int sub  = lane >> 3;
    const int lr   = lane & 7;

    uint32_t sA = smem_u32(As), sB = smem_u32(Bs);

    uint32_t dst_off[2];
    int src_off[2];
    #pragma unroll
    for (int l = 0; l < 2; l++) {
        int v = tid + l * 256;
        int r = v >> 2, c8 = v & 3;
        dst_off[l] = sw_off(r, c8 * 16);
        src_off[l] = r * DK + c8 * 8;
    }
    uint32_t offA[2][4], offB[2][2];
    #pragma unroll
    for (int s = 0; s < 2; s++) {
        int kbA = s * 32 + (sub >> 1) * 16;
        #pragma unroll
        for (int i = 0; i < 4; i++)
            offA[s][i] = sw_off(wm * 64 + i * 16 + (sub & 1) * 8 + lr, kbA);
        int kbB = s * 32 + (sub & 1) * 16;
        #pragma unroll
        for (int jp = 0; jp < 2; jp++)
            offB[s][jp] = sw_off(wn * 32 + jp * 16 + (sub >> 1) * 8 + lr, kbB);
    }

    float acc[4][4][4];
    #pragma unroll
    for (int i = 0; i < 4; i++)
        #pragma unroll
        for (int j = 0; j < 4; j++)
            #pragma unroll
            for (int r = 0; r < 4; r++) acc[i][j][r] = 0.0f;

    const __nv_bfloat16* Abase = g_Fa + (size_t)row0 * DK;
    const __nv_bfloat16* Bbase = g_Fb + (size_t)col0 * DK;

    MAINLOOP(Abase, Bbase, sA, sB)

    // ---- epilogue (rs/rc reuse stage-0 smem; mainloop fully drained) ----
    float* rs = reinterpret_cast<float*>(As);
    float* rc = rs + 128;
    if (tid < 128) { rs[tid] = 0.0f; rc[tid] = 0.0f; }
    __syncthreads();

    const float S2 = 2.8853900817779268f;   // 2/ln2 (1/TEMP = 2)
    float colsum[4][2];
    #pragma unroll
    for (int j = 0; j < 4; j++) { colsum[j][0] = 0.0f; colsum[j][1] = 0.0f; }

    #pragma unroll
    for (int i = 0; i < 4; i++) {
        #pragma unroll
        for (int h = 0; h < 2; h++) {
            int rl = wm * 64 + i * 16 + h * 8 + g;
            int gi = row0 + rl;
            int pj = (gi + BHALF) & (NROW - 1);
            float sum = 0.0f;
            #pragma unroll
            for (int j = 0; j < 4; j++) {
                float e0 = fexp2(acc[i][j][2 * h]     * S2);
                float e1 = fexp2(acc[i][j][2 * h + 1] * S2);
                sum += e0 + e1;
                colsum[j][0] += e0;
                colsum[j][1] += e1;
                int gj = col0 + wn * 32 + j * 8 + 2 * t;
                if (gj == pj)     { g_pos[gi] = e0; if (diffblk) g_pos[gj]     = e0; }
                if (gj + 1 == pj) { g_pos[gi] = e1; if (diffblk) g_pos[gj + 1] = e1; }
            }
            sum += __shfl_xor_sync(0xffffffffu, sum, 1);
            sum += __shfl_xor_sync(0xffffffffu, sum, 2);
            if (t == 0) atomicAdd(&rs[rl], sum);
        }
    }
    if (diffblk) {
        #pragma unroll
        for (int j = 0; j < 4; j++) {
            #pragma unroll
            for (int p = 0; p < 2; p++) {
                float v = colsum[j][p];
                v += __shfl_xor_sync(0xffffffffu, v, 4);
                v += __shfl_xor_sync(0xffffffffu, v, 8);
                v += __shfl_xor_sync(0xffffffffu, v, 16);
                if (g == 0) atomicAdd(&rc[wn * 32 + j * 8 + 2 * t + p], v);
            }
        }
    }
    __syncthreads();
    if (tid < 128) {
        atomicAdd(&g_rowsum[row0 + tid], rs[tid]);
        if (diffblk) atomicAdd(&g_rowsum[col0 + tid], rc[tid]);
    }
}

// ---------------------------------------------------------------------------
// 4) proto GEMM: logits = F @ Cp^T  (4096 x 512, K=384), same engine.
// ---------------------------------------------------------------------------
__global__ void __launch_bounds__(256, 2) proto_bf16() {
    __shared__ __align__(128) __nv_bfloat16 As[3][4096];
    __shared__ __align__(128) __nv_bfloat16 Bs[3][4096];

    const int row0 = blockIdx.y * 128;
    const int col0 = blockIdx.x * 128;
    const int tid  = threadIdx.x;
    const int lane = tid & 31;
    const int w    = tid >> 5;
    const int wm   = w >> 2;
    const int wn   = w & 3;
    const int g    = lane >> 2;
    const int t    = lane & 3;
    const int sub  = lane >> 3;
    const int lr   = lane & 7;

    uint32_t sA = smem_u32(As), sB = smem_u32(Bs);

    uint32_t dst_off[2];
    int src_off[2];
    #pragma unroll
    for (int l = 0; l < 2; l++) {
        int v = tid + l * 256;
        int r = v >> 2, c8 = v & 3;
        dst_off[l] = sw_off(r, c8 * 16);
        src_off[l] = r * DK + c8 * 8;
    }
    uint32_t offA[2][4], offB[2][2];
    #pragma unroll
    for (int s = 0; s < 2; s++) {
        int kbA = s * 32 + (sub >> 1) * 16;
        #pragma unroll
        for (int i = 0; i < 4; i++)
            offA[s][i] = sw_off(wm * 64 + i * 16 + (sub & 1) * 8 + lr, kbA);
        int kbB = s * 32 + (sub & 1) * 16;
        #pragma unroll
        for (int jp = 0; jp < 2; jp++)
            offB[s][jp] = sw_off(wn * 32 + jp * 16 + (sub >> 1) * 8 + lr, kbB);
    }

    float acc[4][4][4];
    #pragma unroll
    for (int i = 0; i < 4; i++)
        #pragma unroll
        for (int j = 0; j < 4; j++)
            #pragma unroll
            for (int r = 0; r < 4; r++) acc[i][j][r] = 0.0f;

    const __nv_bfloat16* Abase = g_Fb + (size_t)row0 * DK;
    const __nv_bfloat16* Bbase = g_Cp + (size_t)col0 * DK;

    MAINLOOP(Abase, Bbase, sA, sB)

    #pragma unroll
    for (int i = 0; i < 4; i++) {
        #pragma unroll
        for (int h = 0; h < 2; h++) {
            int gi = row0 + wm * 64 + i * 16 + h * 8 + g;
            #pragma unroll
            for (int j = 0; j < 4; j++) {
                int gj = col0 + wn * 32 + j * 8 + 2 * t;
                g_logits[(size_t)gi * NC + gj]     = acc[i][j][2 * h];
                g_logits[(size_t)gi * NC + gj + 1] = acc[i][j][2 * h + 1];
            }
        }
    }
}

// ---------------------------------------------------------------------------
// 5) Finalize: per-row logsumexp over 512 logits + contrastive terms -> mean
// ---------------------------------------------------------------------------
__global__ void finalize_kernel(const int* __restrict__ labels, float* __restrict__ out) {
    int row  = (blockIdx.x * blockDim.x + threadIdx.x) >> 5;
    int lane = threadIdx.x & 31;
    if (row >= NROW) return;
    const float* lg = &g_logits[(size_t)row * NC];

    float mx = -1e30f;
    #pragma unroll 4
    for (int j = lane; j < NC; j += 32) mx = fmaxf(mx, lg[j]);
    #pragma unroll
    for (int o = 16; o; o >>= 1) mx = fmaxf(mx, __shfl_xor_sync(0xffffffffu, mx, o));

    const float LOG2E = 1.4426950408889634f;
    float s = 0.0f;
    #pragma unroll 4
    for (int j = lane; j < NC; j += 32) s += fexp2((lg[j] - mx) * LOG2E);
    #pragma unroll
    for (int o = 16; o; o >>= 1) s += __shfl_xor_sync(0xffffffffu, s, o);

    if (lane == 0) {
        float lse   = mx + logf(s);
        int   lab   = labels[row];
        float loss2 = lse - lg[lab];
        float loss1 = logf((g_rowsum[row] - 7.3890560989306495f) / g_pos[row]); // diag=e^2
        atomicAdd(out, (loss1 + loss2) * (1.0f / NROW));
    }
}

// ---------------------------------------------------------------------------
extern "C" void kernel_launch(void* const* d_in, const int* in_sizes, int n_in,
                              void* d_out, int out_size) {
    const float* st_i  = (const float*)d_in[0];
    const float* st_j  = (const float*)d_in[1];
    const float* car_i = (const float*)d_in[2];
    const float* car_j = (const float*)d_in[3];
    const float* pl_i  = (const float*)d_in[4];
    const float* pl_j  = (const float*)d_in[5];
    const int*   lab   = (const int*)d_in[6];
    const float* cst   = (const float*)d_in[7];
    const float* ccar  = (const float*)d_in[8];
    const float* cpl   = (const float*)d_in[9];
    const float* conc  = (const float*)d_in[10];
    float* out = (float*)d_out;

    normalize_kernel<<<(6 * BHALF * 32 + 255) / 256, 256>>>(st_i, st_j, car_i, car_j, pl_i, pl_j);
    cent_kernel<<<(NC * DK + 255) / 256, 256>>>(cst, ccar, cpl, conc, out, out_size);

    sims_bf16<<<528, 256>>>();                 // triangular grid

    dim3 gp(NC / 128, NROW / 128);             // 4 x 32
    proto_bf16<<<gp, 256>>>();

    finalize_kernel<<<(NROW * 32 + 255) / 256, 256>>>(lab, out);
}

// round 6
// speedup vs baseline: 8.3385x; 1.0724x over previous
#include <cuda_runtime.h>
#include <cuda_fp16.h>
#include <math.h>
#include <stdint.h>

// Problem constants
#define NROW 4096
#define BHALF 2048
#define DK   384
#define DMOD 128
#define NC   512

// Scratch (device globals)
__device__ __half g_Fa[NROW * DK];   // weighted normalized features (A operand)
__device__ __half g_Fb[NROW * DK];   // normalized features (B operand)
__device__ __half g_Cp[NC * DK];     // centroids * w_m/(conc+1e-12)
__device__ float g_logits[NROW * NC];
__device__ float g_rowsum[NROW];
__device__ float g_pos[NROW];

// ---------------------------------------------------------------------------
// helpers
// ---------------------------------------------------------------------------
__device__ __forceinline__ uint32_t smem_u32(const void* p) {
    uint32_t a;
    asm("{ .reg .u64 t; cvta.to.shared.u64 t, %1; cvt.u32.u64 %0, t; }" : "=r"(a) : "l"(p));
    return a;
}

// fast exp2 on FMA pipe
__device__ __forceinline__ float fexp2(float t) {
    float r = t + 12582912.0f;
    int   i = __float_as_int(r) - 0x4B400000;
    float f = t - (r - 12582912.0f);
    float p = 1.3333558e-3f;
    p = fmaf(p, f, 9.6181291e-3f);
    p = fmaf(p, f, 5.5504109e-2f);
    p = fmaf(p, f, 2.4022651e-1f);
    p = fmaf(p, f, 6.9314718e-1f);
    p = fmaf(p, f, 1.0f);
    return __int_as_float(__float_as_int(p) + (i << 23));
}

// f32-accumulate fp16 MMA (proto)
__device__ __forceinline__ void mma16816f(float* c, const uint32_t* a, const uint32_t* b) {
    asm volatile(
        "mma.sync.aligned.m16n8k16.row.col.f32.f16.f16.f32 "
        "{%0,%1,%2,%3},{%4,%5,%6,%7},{%8,%9},{%0,%1,%2,%3};"
        : "+f"(c[0]), "+f"(c[1]), "+f"(c[2]), "+f"(c[3])
        : "r"(a[0]), "r"(a[1]), "r"(a[2]), "r"(a[3]), "r"(b[0]), "r"(b[1]));
}
// f16-accumulate fp16 MMA (sims): half the acc registers
__device__ __forceinline__ void mma16816h(uint32_t* c, const uint32_t* a, const uint32_t* b) {
    asm volatile(
        "mma.sync.aligned.m16n8k16.row.col.f16.f16.f16.f16 "
        "{%0,%1},{%2,%3,%4,%5},{%6,%7},{%0,%1};"
        : "+r"(c[0]), "+r"(c[1])
        : "r"(a[0]), "r"(a[1]), "r"(a[2]), "r"(a[3]), "r"(b[0]), "r"(b[1]));
}

#define LDSM_X4(r0, r1, r2, r3, addr) \
    asm volatile("ldmatrix.sync.aligned.m8n8.x4.shared.b16 {%0,%1,%2,%3}, [%4];" \
                 : "=r"(r0), "=r"(r1), "=r"(r2), "=r"(r3) : "r"(addr))

// Packed tile layout: rows x 32 fp16 (64B/row), two rows per 128B line,
// XOR swizzle -> conflict-free for cp.async fill and ldmatrix.
__device__ __forceinline__ uint32_t sw_off(int r, int kb) {
    uint32_t L = ((uint32_t)(r >> 1) << 7) | ((uint32_t)(r & 1) << 6) | (uint32_t)kb;
    return L ^ ((L >> 3) & 0x70);
}

#define KTILES 12          // 384 / 32
#define CPA(dst, src) \
    asm volatile("cp.async.cg.shared.global [%0], [%1], 16;" :: "r"(dst), "l"(src))

// ---------------------------------------------------------------------------
// 0) prologue: normalize features (blocks < 1536) + centroid scale / zero
// ---------------------------------------------------------------------------
__global__ void prep_kernel(const float* __restrict__ st_i,
                            const float* __restrict__ st_j,
                            const float* __restrict__ car_i,
                            const float* __restrict__ car_j,
                            const float* __restrict__ pl_i,
                            const float* __restrict__ pl_j,
                            const float* __restrict__ cst,
                            const float* __restrict__ ccar,
                            const float* __restrict__ cpl,
                            const float* __restrict__ conc,
                            float* __restrict__ out, int out_size) {
    int b = blockIdx.x;
    if (b < 1536) {
        int g = b * 8 + (threadIdx.x >> 5);
        int lane = threadIdx.x & 31;
        int t = g / BHALF;
        int r = g % BHALF;
        const float* src;
        switch (t) {
            case 0: src = st_i;  break;
            case 1: src = st_j;  break;
            case 2: src = car_i; break;
            case 3: src = car_j; break;
            case 4: src = pl_i;  break;
            default: src = pl_j; break;
        }
        int m    = t >> 1;
        int half = t & 1;
        float w  = (m == 0) ? 0.4f : 0.3f;

        float4 v = *reinterpret_cast<const float4*>(&src[(size_t)r * DMOD + lane * 4]);
        float ss = v.x * v.x + v.y * v.y + v.z * v.z + v.w * v.w;
        #pragma unroll
        for (int o = 16; o; o >>= 1) ss += __shfl_xor_sync(0xffffffffu, ss, o);
        float scale = 1.0f / fmaxf(sqrtf(ss), 1e-12f);
        float ws = scale * w;

        int grow = half * BHALF + r;
        size_t base = (size_t)grow * DK + m * DMOD + lane * 4;
        *reinterpret_cast<__half2*>(&g_Fb[base])     = __floats2half2_rn(v.x * scale, v.y * scale);
        *reinterpret_cast<__half2*>(&g_Fb[base + 2]) = __floats2half2_rn(v.z * scale, v.w * scale);
        *reinterpret_cast<__half2*>(&g_Fa[base])     = __floats2half2_rn(v.x * ws, v.y * ws);
        *reinterpret_cast<__half2*>(&g_Fa[base + 2]) = __floats2half2_rn(v.z * ws, v.w * ws);
    } else {
        int idx = (b - 1536) * 256 + threadIdx.x;
        if (idx < NROW) g_rowsum[idx] = 0.0f;
        if (idx < out_size) out[idx] = 0.0f;
        if (idx < NC * DK) {
            int c   = idx / DK;
            int rem = idx % DK;
            int m   = rem >> 7;
            int d   = rem & 127;
            const float* cen = (m == 0) ? cst : ((m == 1) ? ccar : cpl);
            float w = (m == 0) ? 0.4f : 0.3f;
            g_Cp[idx] = __float2half_rn(cen[c * DMOD + d] * (w / (conc[m * NC + c] + 1e-12f)));
        }
    }
}

// ---------------------------------------------------------------------------
// 1) sims GEMM: S = (wF) @ F^T, 128x128 tiles, triangular grid (528 CTAs),
//    fp16 inputs, fp16 accumulators, 3-stage cp.async, 1 barrier/iter.
// ---------------------------------------------------------------------------
__global__ void __launch_bounds__(256, 3) sims_f16() {
    __shared__ __align__(128) __half As[3][4096];   // 8 KB/stage
    __shared__ __align__(128) __half Bs[3][4096];

    // triangular decode: (by, bx) with bx >= by
    int n = blockIdx.x;
    int by = 0;
    while (n >= 32 - by) { n -= 32 - by; by++; }
    int bx = by + n;
    const bool diffblk = (bx != by);
    const int row0 = by * 128, col0 = bx * 128;

    const int tid  = threadIdx.x;
    const int lane = tid & 31;
    const int w    = tid >> 5;
    const int wm   = w >> 2;
    const int wn   = w & 3;
    const int g    = lane >> 2;
    const int t    = lane & 3;
    const int sub  = lane >> 3;
    const int lr   = lane & 7;

    uint32_t sA = smem_u32(As), sB = smem_u32(Bs);

    uint32_t dst_off[2];
    int src_off[2];
    #pragma unroll
    for (int l = 0; l < 2; l++) {
        int v = tid + l * 256;
        int r = v >> 2, c8 = v & 3;
        dst_off[l] = sw_off(r, c8 * 16);
        src_off[l] = r * DK + c8 * 8;
    }
    uint32_t offA[2][4], offB[2][2];
    #pragma unroll
    for (int s = 0; s < 2; s++) {
        int kbA = s * 32 + (sub >> 1) * 16;
        #pragma unroll
        for (int i = 0; i < 4; i++)
            offA[s][i] = sw_off(wm * 64 + i * 16 + (sub & 1) * 8 + lr, kbA);
        int kbB = s * 32 + (sub & 1) * 16;
        #pragma unroll
        for (int jp = 0; jp < 2; jp++)
            offB[s][jp] = sw_off(wn * 32 + jp * 16 + (sub >> 1) * 8 + lr, kbB);
    }

    uint32_t acc[4][4][2];
    #pragma unroll
    for (int i = 0; i < 4; i++)
        #pragma unroll
        for (int j = 0; j < 4; j++) { acc[i][j][0] = 0u; acc[i][j][1] = 0u; }

    const __half* Abase = g_Fa + (size_t)row0 * DK;
    const __half* Bbase = g_Fb + (size_t)col0 * DK;

    // prefetch stages 0,1
    #pragma unroll
    for (int pf = 0; pf < 2; pf++) {
        #pragma unroll
        for (int l = 0; l < 2; l++) {
            CPA(sA + pf * 8192 + dst_off[l], __cvta_generic_to_global(Abase + pf * 32 + src_off[l]));
            CPA(sB + pf * 8192 + dst_off[l], __cvta_generic_to_global(Bbase + pf * 32 + src_off[l]));
        }
        asm volatile("cp.async.commit_group;" ::: "memory");
    }
    #pragma unroll 1
    for (int it = 0; it < KTILES; it++) {
        if (it < KTILES - 1) asm volatile("cp.async.wait_group 1;" ::: "memory");
        else                 asm volatile("cp.async.wait_group 0;" ::: "memory");
        __syncthreads();
        if (it + 2 < KTILES) {
            int st = (it + 2) % 3;
            #pragma unroll
            for (int l = 0; l < 2; l++) {
                CPA(sA + st * 8192 + dst_off[l], __cvta_generic_to_global(Abase + (it + 2) * 32 + src_off[l]));
                CPA(sB + st * 8192 + dst_off[l], __cvta_generic_to_global(Bbase + (it + 2) * 32 + src_off[l]));
            }
            asm volatile("cp.async.commit_group;" ::: "memory");
        }
        uint32_t bA = sA + (it % 3) * 8192, bB = sB + (it % 3) * 8192;
        #pragma unroll
        for (int s = 0; s < 2; s++) {
            uint32_t a[4][4], b[4][2];
            #pragma unroll
            for (int i = 0; i < 4; i++)
                LDSM_X4(a[i][0], a[i][1], a[i][2], a[i][3], bA + offA[s][i]);
            #pragma unroll
            for (int jp = 0; jp < 2; jp++)
                LDSM_X4(b[2 * jp][0], b[2 * jp][1], b[2 * jp + 1][0], b[2 * jp + 1][1],
                        bB + offB[s][jp]);
            #pragma unroll
            for (int i = 0; i < 4; i++)
                #pragma unroll
                for (int j = 0; j < 4; j++)
                    mma16816h(acc[i][j], a[i], b[j]);
        }
    }
    __syncthreads();

    // ---- epilogue (rs/rc reuse stage-0 smem) ----
    float* rs = reinterpret_cast<float*>(As);
    float* rc = rs + 128;
    if (tid < 128) { rs[tid] = 0.0f; rc[tid] = 0.0f; }
    __syncthreads();

    const float S2 = 2.8853900817779268f;   // 2/ln2 (1/TEMP = 2)
    float colsum[4][2];
    #pragma unroll
    for (int j = 0; j < 4; j++) { colsum[j][0] = 0.0f; colsum[j][1] = 0.0f; }

    #pragma unroll
    for (int i = 0; i < 4; i++) {
        #pragma unroll
        for (int h = 0; h < 2; h++) {
            int rl = wm * 64 + i * 16 + h * 8 + g;
            int gi = row0 + rl;
            int pj = (gi + BHALF) & (NROW - 1);
            float sum = 0.0f;
            #pragma unroll
            for (int j = 0; j < 4; j++) {
                float2 sv = __half22float2(*reinterpret_cast<__half2*>(&acc[i][j][h]));
                float e0 = fexp2(sv.x * S2);
                float e1 = fexp2(sv.y * S2);
                sum += e0 + e1;
                colsum[j][0] += e0;
                colsum[j][1] += e1;
                int gj = col0 + wn * 32 + j * 8 + 2 * t;
                if (gj == pj)     { g_pos[gi] = e0; if (diffblk) g_pos[gj]     = e0; }
                if (gj + 1 == pj) { g_pos[gi] = e1; if (diffblk) g_pos[gj + 1] = e1; }
            }
            sum += __shfl_xor_sync(0xffffffffu, sum, 1);
            sum += __shfl_xor_sync(0xffffffffu, sum, 2);
            if (t == 0) atomicAdd(&rs[rl], sum);
        }
    }
    if (diffblk) {
        #pragma unroll
        for (int j = 0; j < 4; j++) {
            #pragma unroll
            for (int p = 0; p < 2; p++) {
                float v = colsum[j][p];
                v += __shfl_xor_sync(0xffffffffu, v, 4);
                v += __shfl_xor_sync(0xffffffffu, v, 8);
                v += __shfl_xor_sync(0xffffffffu, v, 16);
                if (g == 0) atomicAdd(&rc[wn * 32 + j * 8 + 2 * t + p], v);
            }
        }
    }
    __syncthreads();
    if (tid < 128) {
        atomicAdd(&g_rowsum[row0 + tid], rs[tid]);
        if (diffblk) atomicAdd(&g_rowsum[col0 + tid], rc[tid]);
    }
}

// ---------------------------------------------------------------------------
// 2) proto GEMM: logits = F @ Cp^T (4096x512, K=384).
//    64x128 tiles -> 256 CTAs, warp tile 32x32, f32 accumulate.
// ---------------------------------------------------------------------------
__global__ void __launch_bounds__(256, 3) proto_f16() {
    __shared__ __align__(128) __half As[3][2048];   // 4 KB/stage
    __shared__ __align__(128) __half Bs[3][4096];   // 8 KB/stage

    const int row0 = blockIdx.y * 64;
    const int col0 = blockIdx.x * 128;
    const int tid  = threadIdx.x;
    const int lane = tid & 31;
    const int w    = tid >> 5;
    const int wm   = w >> 2;
    const int wn   = w & 3;
    const int g    = lane >> 2;
    const int t    = lane & 3;
    const int sub  = lane >> 3;
    const int lr   = lane & 7;

    uint32_t sA = smem_u32(As), sB = smem_u32(Bs);

    // A: 64x32 -> 256 uint4 (1/thread); B: 128x32 -> 512 uint4 (2/thread)
    uint32_t dstA;
    int srcA;
    {
        int r = tid >> 2, c8 = tid & 3;
        dstA = sw_off(r, c8 * 16);
        srcA = r * DK + c8 * 8;
    }
    uint32_t dstB[2];
    int srcB[2];
    #pragma unroll
    for (int l = 0; l < 2; l++) {
        int v = tid + l * 256;
        int r = v >> 2, c8 = v & 3;
        dstB[l] = sw_off(r, c8 * 16);
        srcB[l] = r * DK + c8 * 8;
    }
    uint32_t offA[2][2], offB[2][2];
    #pragma unroll
    for (int s = 0; s < 2; s++) {
        int kbA = s * 32 + (sub >> 1) * 16;
        #pragma unroll
        for (int i = 0; i < 2; i++)
            offA[s][i] = sw_off(wm * 32 + i * 16 + (sub & 1) * 8 + lr, kbA);
        int kbB = s * 32 + (sub & 1) * 16;
        #pragma unroll
        for (int jp = 0; jp < 2; jp++)
            offB[s][jp] = sw_off(wn * 32 + jp * 16 + (sub >> 1) * 8 + lr, kbB);
    }

    float acc[2][4][4];
    #pragma unroll
    for (int i = 0; i < 2; i++)
        #pragma unroll
        for (int j = 0; j < 4; j++)
            #pragma unroll
            for (int r = 0; r < 4; r++) acc[i][j][r] = 0.0f;

    const __half* Abase = g_Fb + (size_t)row0 * DK;
    const __half* Bbase = g_Cp + (size_t)col0 * DK;

    #pragma unroll
    for (int pf = 0; pf < 2; pf++) {
        CPA(sA + pf * 4096 + dstA, __cvta_generic_to_global(Abase + pf * 32 + srcA));
        #pragma unroll
        for (int l = 0; l < 2; l++)
            CPA(sB + pf * 8192 + dstB[l], __cvta_generic_to_global(Bbase + pf * 32 + srcB[l]));
        asm volatile("cp.async.commit_group;" ::: "memory");
    }
    #pragma unroll 1
    for (int it = 0; it < KTILES; it++) {
        if (it < KTILES - 1) asm volatile("cp.async.wait_group 1;" ::: "memory");
        else                 asm volatile("cp.async.wait_group 0;" ::: "memory");
        __syncthreads();
        if (it + 2 < KTILES) {
            int st = (it + 2) % 3;
            CPA(sA + st * 4096 + dstA, __cvta_generic_to_global(Abase + (it + 2) * 32 + srcA));
            #pragma unroll
            for (int l = 0; l < 2; l++)
                CPA(sB + st * 8192 + dstB[l], __cvta_generic_to_global(Bbase + (it + 2) * 32 + srcB[l]));
            asm volatile("cp.async.commit_group;" ::: "memory");
        }
        uint32_t bA = sA + (it % 3) * 4096, bB = sB + (it % 3) * 8192;
        #pragma unroll
        for (int s = 0; s < 2; s++) {
            uint32_t a[2][4], b[4][2];
            #pragma unroll
            for (int i = 0; i < 2; i++)
                LDSM_X4(a[i][0], a[i][1], a[i][2], a[i][3], bA + offA[s][i]);
            #pragma unroll
            for (int jp = 0; jp < 2; jp++)
                LDSM_X4(b[2 * jp][0], b[2 * jp][1], b[2 * jp + 1][0], b[2 * jp + 1][1],
                        bB + offB[s][jp]);
            #pragma unroll
            for (int i = 0; i < 2; i++)
                #pragma unroll
                for (int j = 0; j < 4; j++)
                    mma16816f(acc[i][j], a[i], b[j]);
        }
    }

    #pragma unroll
    for (int i = 0; i < 2; i++) {
        #pragma unroll
        for (int h = 0; h < 2; h++) {
            int gi = row0 + wm * 32 + i * 16 + h * 8 + g;
            #pragma unroll
            for (int j = 0; j < 4; j++) {
                int gj = col0 + wn * 32 + j * 8 + 2 * t;
                g_logits[(size_t)gi * NC + gj]     = acc[i][j][2 * h];
                g_logits[(size_t)gi * NC + gj + 1] = acc[i][j][2 * h + 1];
            }
        }
    }
}

// ---------------------------------------------------------------------------
// 3) Finalize: per-row logsumexp over 512 logits + contrastive terms -> mean
// ---------------------------------------------------------------------------
__global__ void finalize_kernel(const int* __restrict__ labels, float* __restrict__ out) {
    int row  = (blockIdx.x * blockDim.x + threadIdx.x) >> 5;
    int lane = threadIdx.x & 31;
    if (row >= NROW) return;
    const float* lg = &g_logits[(size_t)row * NC];

    float mx = -1e30f;
    #pragma unroll 4
    for (int j = lane; j < NC; j += 32) mx = fmaxf(mx, lg[j]);
    #pragma unroll
    for (int o = 16; o; o >>= 1) mx = fmaxf(mx, __shfl_xor_sync(0xffffffffu, mx, o));

    const float LOG2E = 1.4426950408889634f;
    float s = 0.0f;
    #pragma unroll 4
    for (int j = lane; j < NC; j += 32) s += fexp2((lg[j] - mx) * LOG2E);
    #pragma unroll
    for (int o = 16; o; o >>= 1) s += __shfl_xor_sync(0xffffffffu, s, o);

    if (lane == 0) {
        float lse   = mx + logf(s);
        int   lab   = labels[row];
        float loss2 = lse - lg[lab];
        float loss1 = logf((g_rowsum[row] - 7.3890560989306495f) / g_pos[row]); // diag=e^2
        atomicAdd(out, (loss1 + loss2) * (1.0f / NROW));
    }
}

// ---------------------------------------------------------------------------
extern "C" void kernel_launch(void* const* d_in, const int* in_sizes, int n_in,
                              void* d_out, int out_size) {
    const float* st_i  = (const float*)d_in[0];
    const float* st_j  = (const float*)d_in[1];
    const float* car_i = (const float*)d_in[2];
    const float* car_j = (const float*)d_in[3];
    const float* pl_i  = (const float*)d_in[4];
    const float* pl_j  = (const float*)d_in[5];
    const int*   lab   = (const int*)d_in[6];
    const float* cst   = (const float*)d_in[7];
    const float* ccar  = (const float*)d_in[8];
    const float* cpl   = (const float*)d_in[9];
    const float* conc  = (const float*)d_in[10];
    float* out = (float*)d_out;

    prep_kernel<<<1536 + 768, 256>>>(st_i, st_j, car_i, car_j, pl_i, pl_j,
                                     cst, ccar, cpl, conc, out, out_size);

    sims_f16<<<528, 256>>>();                  // triangular grid

    dim3 gp(NC / 128, NROW / 64);              // 4 x 64 = 256 CTAs
    proto_f16<<<gp, 256>>>();

    finalize_kernel<<<(NROW * 32 + 255) / 256, 256>>>(lab, out);
}

// round 7
// speedup vs baseline: 9.7929x; 1.1744x over previous
#include <cuda_runtime.h>
#include <cuda_fp16.h>
#include <math.h>
#include <stdint.h>

// Problem constants
#define NROW 4096
#define BHALF 2048
#define DK   384
#define DMOD 128
#define NC   512

// Scratch (device globals)
__device__ __half g_Fa[NROW * DK];   // weighted normalized features (A operand)
__device__ __half g_Fb[NROW * DK];   // normalized features (B operand)
__device__ __half g_Cp[NC * DK];     // centroids * w_m/(conc+1e-12)
__device__ float g_rowsum[NROW];
__device__ float g_pos[NROW];
__device__ float g_sumexp[NROW];     // proto row sum of exp(logit)
__device__ float g_labval[NROW];     // proto logit at the label column

// ---------------------------------------------------------------------------
// helpers
// ---------------------------------------------------------------------------
__device__ __forceinline__ uint32_t smem_u32(const void* p) {
    uint32_t a;
    asm("{ .reg .u64 t; cvta.to.shared.u64 t, %1; cvt.u32.u64 %0, t; }" : "=r"(a) : "l"(p));
    return a;
}

// fast exp2 on FMA pipe
__device__ __forceinline__ float fexp2(float t) {
    float r = t + 12582912.0f;
    int   i = __float_as_int(r) - 0x4B400000;
    float f = t - (r - 12582912.0f);
    float p = 1.3333558e-3f;
    p = fmaf(p, f, 9.6181291e-3f);
    p = fmaf(p, f, 5.5504109e-2f);
    p = fmaf(p, f, 2.4022651e-1f);
    p = fmaf(p, f, 6.9314718e-1f);
    p = fmaf(p, f, 1.0f);
    return __int_as_float(__float_as_int(p) + (i << 23));
}

// f32-accumulate fp16 MMA (proto)
__device__ __forceinline__ void mma16816f(float* c, const uint32_t* a, const uint32_t* b) {
    asm volatile(
        "mma.sync.aligned.m16n8k16.row.col.f32.f16.f16.f32 "
        "{%0,%1,%2,%3},{%4,%5,%6,%7},{%8,%9},{%0,%1,%2,%3};"
        : "+f"(c[0]), "+f"(c[1]), "+f"(c[2]), "+f"(c[3])
        : "r"(a[0]), "r"(a[1]), "r"(a[2]), "r"(a[3]), "r"(b[0]), "r"(b[1]));
}
// f16-accumulate fp16 MMA (sims)
__device__ __forceinline__ void mma16816h(uint32_t* c, const uint32_t* a, const uint32_t* b) {
    asm volatile(
        "mma.sync.aligned.m16n8k16.row.col.f16.f16.f16.f16 "
        "{%0,%1},{%2,%3,%4,%5},{%6,%7},{%0,%1};"
        : "+r"(c[0]), "+r"(c[1])
        : "r"(a[0]), "r"(a[1]), "r"(a[2]), "r"(a[3]), "r"(b[0]), "r"(b[1]));
}

#define LDSM_X4(r0, r1, r2, r3, addr) \
    asm volatile("ldmatrix.sync.aligned.m8n8.x4.shared.b16 {%0,%1,%2,%3}, [%4];" \
                 : "=r"(r0), "=r"(r1), "=r"(r2), "=r"(r3) : "r"(addr))

// Packed tile layout: rows x 32 fp16 (64B/row), two rows per 128B line,
// XOR swizzle -> conflict-free for cp.async fill and ldmatrix.
__device__ __forceinline__ uint32_t sw_off(int r, int kb) {
    uint32_t L = ((uint32_t)(r >> 1) << 7) | ((uint32_t)(r & 1) << 6) | (uint32_t)kb;
    return L ^ ((L >> 3) & 0x70);
}

#define KTILES 12          // 384 / 32
#define CPA(dst, src) \
    asm volatile("cp.async.cg.shared.global [%0], [%1], 16;" :: "r"(dst), "l"(src))

// ---------------------------------------------------------------------------
// 0) prologue: normalize features (blocks < 1536) + centroid scale / zero
// ---------------------------------------------------------------------------
__global__ void prep_kernel(const float* __restrict__ st_i,
                            const float* __restrict__ st_j,
                            const float* __restrict__ car_i,
                            const float* __restrict__ car_j,
                            const float* __restrict__ pl_i,
                            const float* __restrict__ pl_j,
                            const float* __restrict__ cst,
                            const float* __restrict__ ccar,
                            const float* __restrict__ cpl,
                            const float* __restrict__ conc,
                            float* __restrict__ out, int out_size) {
    int b = blockIdx.x;
    if (b < 1536) {
        int g = b * 8 + (threadIdx.x >> 5);
        int lane = threadIdx.x & 31;
        int t = g / BHALF;
        int r = g % BHALF;
        const float* src;
        switch (t) {
            case 0: src = st_i;  break;
            case 1: src = st_j;  break;
            case 2: src = car_i; break;
            case 3: src = car_j; break;
            case 4: src = pl_i;  break;
            default: src = pl_j; break;
        }
        int m    = t >> 1;
        int half = t & 1;
        float w  = (m == 0) ? 0.4f : 0.3f;

        float4 v = *reinterpret_cast<const float4*>(&src[(size_t)r * DMOD + lane * 4]);
        float ss = v.x * v.x + v.y * v.y + v.z * v.z + v.w * v.w;
        #pragma unroll
        for (int o = 16; o; o >>= 1) ss += __shfl_xor_sync(0xffffffffu, ss, o);
        float scale = 1.0f / fmaxf(sqrtf(ss), 1e-12f);
        float ws = scale * w;

        int grow = half * BHALF + r;
        size_t base = (size_t)grow * DK + m * DMOD + lane * 4;
        *reinterpret_cast<__half2*>(&g_Fb[base])     = __floats2half2_rn(v.x * scale, v.y * scale);
        *reinterpret_cast<__half2*>(&g_Fb[base + 2]) = __floats2half2_rn(v.z * scale, v.w * scale);
        *reinterpret_cast<__half2*>(&g_Fa[base])     = __floats2half2_rn(v.x * ws, v.y * ws);
        *reinterpret_cast<__half2*>(&g_Fa[base + 2]) = __floats2half2_rn(v.z * ws, v.w * ws);
    } else {
        int idx = (b - 1536) * 256 + threadIdx.x;
        if (idx < NROW) { g_rowsum[idx] = 0.0f; g_sumexp[idx] = 0.0f; }
        if (idx < out_size) out[idx] = 0.0f;
        if (idx < NC * DK) {
            int c   = idx / DK;
            int rem = idx % DK;
            int m   = rem >> 7;
            int d   = rem & 127;
            const float* cen = (m == 0) ? cst : ((m == 1) ? ccar : cpl);
            float w = (m == 0) ? 0.4f : 0.3f;
            g_Cp[idx] = __float2half_rn(cen[c * DMOD + d] * (w / (conc[m * NC + c] + 1e-12f)));
        }
    }
}

// ---------------------------------------------------------------------------
// 1) sims GEMM: S = (wF) @ F^T, 128x128 tiles, triangular grid (528 CTAs),
//    fp16 inputs, fp16 accumulators, 3-stage cp.async, 1 barrier/iter.
// ---------------------------------------------------------------------------
__global__ void __launch_bounds__(256, 3) sims_f16() {
    __shared__ __align__(128) __half As[3][4096];   // 8 KB/stage
    __shared__ __align__(128) __half Bs[3][4096];

    // triangular decode: (by, bx) with bx >= by
    int n = blockIdx.x;
    int by = 0;
    while (n >= 32 - by) { n -= 32 - by; by++; }
    int bx = by + n;
    const bool diffblk = (bx != by);
    const int row0 = by * 128, col0 = bx * 128;

    const int tid  = threadIdx.x;
    const int lane = tid & 31;
    const int w    = tid >> 5;
    const int wm   = w >> 2;
    const int wn   = w & 3;
    const int g    = lane >> 2;
    const int t    = lane & 3;
    const int sub  = lane >> 3;
    const int lr   = lane & 7;

    uint32_t sA = smem_u32(As), sB = smem_u32(Bs);

    uint32_t dst_off[2];
    int src_off[2];
    #pragma unroll
    for (int l = 0; l < 2; l++) {
        int v = tid + l * 256;
        int r = v >> 2, c8 = v & 3;
        dst_off[l] = sw_off(r, c8 * 16);
        src_off[l] = r * DK + c8 * 8;
    }
    uint32_t offA[2][4], offB[2][2];
    #pragma unroll
    for (int s = 0; s < 2; s++) {
        int kbA = s * 32 + (sub >> 1) * 16;
        #pragma unroll
        for (int i = 0; i < 4; i++)
            offA[s][i] = sw_off(wm * 64 + i * 16 + (sub & 1) * 8 + lr, kbA);
        int kbB = s * 32 + (sub & 1) * 16;
        #pragma unroll
        for (int jp = 0; jp < 2; jp++)
            offB[s][jp] = sw_off(wn * 32 + jp * 16 + (sub >> 1) * 8 + lr, kbB);
    }

    uint32_t acc[4][4][2];
    #pragma unroll
    for (int i = 0; i < 4; i++)
        #pragma unroll
        for (int j = 0; j < 4; j++) { acc[i][j][0] = 0u; acc[i][j][1] = 0u; }

    const __half* Abase = g_Fa + (size_t)row0 * DK;
    const __half* Bbase = g_Fb + (size_t)col0 * DK;

    #pragma unroll
    for (int pf = 0; pf < 2; pf++) {
        #pragma unroll
        for (int l = 0; l < 2; l++) {
            CPA(sA + pf * 8192 + dst_off[l], __cvta_generic_to_global(Abase + pf * 32 + src_off[l]));
            CPA(sB + pf * 8192 + dst_off[l], __cvta_generic_to_global(Bbase + pf * 32 + src_off[l]));
        }
        asm volatile("cp.async.commit_group;" ::: "memory");
    }
    #pragma unroll 1
    for (int it = 0; it < KTILES; it++) {
        if (it < KTILES - 1) asm volatile("cp.async.wait_group 1;" ::: "memory");
        else                 asm volatile("cp.async.wait_group 0;" ::: "memory");
        __syncthreads();
        if (it + 2 < KTILES) {
            int st = (it + 2) % 3;
            #pragma unroll
            for (int l = 0; l < 2; l++) {
                CPA(sA + st * 8192 + dst_off[l], __cvta_generic_to_global(Abase + (it + 2) * 32 + src_off[l]));
                CPA(sB + st * 8192 + dst_off[l], __cvta_generic_to_global(Bbase + (it + 2) * 32 + src_off[l]));
            }
            asm volatile("cp.async.commit_group;" ::: "memory");
        }
        uint32_t bA = sA + (it % 3) * 8192, bB = sB + (it % 3) * 8192;
        #pragma unroll
        for (int s = 0; s < 2; s++) {
            uint32_t a[4][4], b[4][2];
            #pragma unroll
            for (int i = 0; i < 4; i++)
                LDSM_X4(a[i][0], a[i][1], a[i][2], a[i][3], bA + offA[s][i]);
            #pragma unroll
            for (int jp = 0; jp < 2; jp++)
                LDSM_X4(b[2 * jp][0], b[2 * jp][1], b[2 * jp + 1][0], b[2 * jp + 1][1],
                        bB + offB[s][jp]);
            #pragma unroll
            for (int i = 0; i < 4; i++)
                #pragma unroll
                for (int j = 0; j < 4; j++)
                    mma16816h(acc[i][j], a[i], b[j]);
        }
    }
    __syncthreads();

    // ---- epilogue (rs/rc reuse stage-0 smem) ----
    float* rs = reinterpret_cast<float*>(As);
    float* rc = rs + 128;
    if (tid < 128) { rs[tid] = 0.0f; rc[tid] = 0.0f; }
    __syncthreads();

    const float S2 = 2.8853900817779268f;   // 2/ln2 (1/TEMP = 2)
    float colsum[4][2];
    #pragma unroll
    for (int j = 0; j < 4; j++) { colsum[j][0] = 0.0f; colsum[j][1] = 0.0f; }

    #pragma unroll
    for (int i = 0; i < 4; i++) {
        #pragma unroll
        for (int h = 0; h < 2; h++) {
            int rl = wm * 64 + i * 16 + h * 8 + g;
            int gi = row0 + rl;
            int pj = (gi + BHALF) & (NROW - 1);
            float sum = 0.0f;
            #pragma unroll
            for (int j = 0; j < 4; j++) {
                float2 sv = __half22float2(*reinterpret_cast<__half2*>(&acc[i][j][h]));
                float e0 = fexp2(sv.x * S2);
                float e1 = fexp2(sv.y * S2);
                sum += e0 + e1;
                colsum[j][0] += e0;
                colsum[j][1] += e1;
                int gj = col0 + wn * 32 + j * 8 + 2 * t;
                if (gj == pj)     { g_pos[gi] = e0; if (diffblk) g_pos[gj]     = e0; }
                if (gj + 1 == pj) { g_pos[gi] = e1; if (diffblk) g_pos[gj + 1] = e1; }
            }
            sum += __shfl_xor_sync(0xffffffffu, sum, 1);
            sum += __shfl_xor_sync(0xffffffffu, sum, 2);
            if (t == 0) atomicAdd(&rs[rl], sum);
        }
    }
    if (diffblk) {
        #pragma unroll
        for (int j = 0; j < 4; j++) {
            #pragma unroll
            for (int p = 0; p < 2; p++) {
                float v = colsum[j][p];
                v += __shfl_xor_sync(0xffffffffu, v, 4);
                v += __shfl_xor_sync(0xffffffffu, v, 8);
                v += __shfl_xor_sync(0xffffffffu, v, 16);
                if (g == 0) atomicAdd(&rc[wn * 32 + j * 8 + 2 * t + p], v);
            }
        }
    }
    __syncthreads();
    if (tid < 128) {
        atomicAdd(&g_rowsum[row0 + tid], rs[tid]);
        if (diffblk) atomicAdd(&g_rowsum[col0 + tid], rc[tid]);
    }
}

// ---------------------------------------------------------------------------
// 2) proto GEMM + fused softmax: logits = F @ Cp^T (4096x512, K=384).
//    64x128 tiles -> 256 CTAs. Logits are bounded (|l| < ~40) so sum-exp
//    needs no max subtraction -> distributive over column tiles: each CTA
//    atomically accumulates exp-sums per row; label logit stored directly.
//    No 8 MB logits round-trip.
// ---------------------------------------------------------------------------
__global__ void __launch_bounds__(256, 3) proto_f16(const int* __restrict__ labels) {
    __shared__ __align__(128) __half As[3][2048];   // 4 KB/stage
    __shared__ __align__(128) __half Bs[3][4096];   // 8 KB/stage

    const int row0 = blockIdx.y * 64;
    const int col0 = blockIdx.x * 128;
    const int tid  = threadIdx.x;
    const int lane = tid & 31;
    const int w    = tid >> 5;
    const int wm   = w >> 2;
    const int wn   = w & 3;
    const int g    = lane >> 2;
    const int t    = lane & 3;
    const int sub  = lane >> 3;
    const int lr   = lane & 7;

    uint32_t sA = smem_u32(As), sB = smem_u32(Bs);

    uint32_t dstA;
    int srcA;
    {
        int r = tid >> 2, c8 = tid & 3;
        dstA = sw_off(r, c8 * 16);
        srcA = r * DK + c8 * 8;
    }
    uint32_t dstB[2];
    int srcB[2];
    #pragma unroll
    for (int l = 0; l < 2; l++) {
        int v = tid + l * 256;
        int r = v >> 2, c8 = v & 3;
        dstB[l] = sw_off(r, c8 * 16);
        srcB[l] = r * DK + c8 * 8;
    }
    uint32_t offA[2][2], offB[2][2];
    #pragma unroll
    for (int s = 0; s < 2; s++) {
        int kbA = s * 32 + (sub >> 1) * 16;
        #pragma unroll
        for (int i = 0; i < 2; i++)
            offA[s][i] = sw_off(wm * 32 + i * 16 + (sub & 1) * 8 + lr, kbA);
        int kbB = s * 32 + (sub & 1) * 16;
        #pragma unroll
        for (int jp = 0; jp < 2; jp++)
            offB[s][jp] = sw_off(wn * 32 + jp * 16 + (sub >> 1) * 8 + lr, kbB);
    }

    float acc[2][4][4];
    #pragma unroll
    for (int i = 0; i < 2; i++)
        #pragma unroll
        for (int j = 0; j < 4; j++)
            #pragma unroll
            for (int r = 0; r < 4; r++) acc[i][j][r] = 0.0f;

    const __half* Abase = g_Fb + (size_t)row0 * DK;
    const __half* Bbase = g_Cp + (size_t)col0 * DK;

    #pragma unroll
    for (int pf = 0; pf < 2; pf++) {
        CPA(sA + pf * 4096 + dstA, __cvta_generic_to_global(Abase + pf * 32 + srcA));
        #pragma unroll
        for (int l = 0; l < 2; l++)
            CPA(sB + pf * 8192 + dstB[l], __cvta_generic_to_global(Bbase + pf * 32 + srcB[l]));
        asm volatile("cp.async.commit_group;" ::: "memory");
    }
    #pragma unroll 1
    for (int it = 0; it < KTILES; it++) {
        if (it < KTILES - 1) asm volatile("cp.async.wait_group 1;" ::: "memory");
        else                 asm volatile("cp.async.wait_group 0;" ::: "memory");
        __syncthreads();
        if (it + 2 < KTILES) {
            int st = (it + 2) % 3;
            CPA(sA + st * 4096 + dstA, __cvta_generic_to_global(Abase + (it + 2) * 32 + srcA));
            #pragma unroll
            for (int l = 0; l < 2; l++)
                CPA(sB + st * 8192 + dstB[l], __cvta_generic_to_global(Bbase + (it + 2) * 32 + srcB[l]));
            asm volatile("cp.async.commit_group;" ::: "memory");
        }
        uint32_t bA = sA + (it % 3) * 4096, bB = sB + (it % 3) * 8192;
        #pragma unroll
        for (int s = 0; s < 2; s++) {
            uint32_t a[2][4], b[4][2];
            #pragma unroll
            for (int i = 0; i < 2; i++)
                LDSM_X4(a[i][0], a[i][1], a[i][2], a[i][3], bA + offA[s][i]);
            #pragma unroll
            for (int jp = 0; jp < 2; jp++)
                LDSM_X4(b[2 * jp][0], b[2 * jp][1], b[2 * jp + 1][0], b[2 * jp + 1][1],
                        bB + offB[s][jp]);
            #pragma unroll
            for (int i = 0; i < 2; i++)
                #pragma unroll
                for (int j = 0; j < 4; j++)
                    mma16816f(acc[i][j], a[i], b[j]);
        }
    }

    // ---- fused softmax epilogue ----
    const float LOG2E = 1.4426950408889634f;
    #pragma unroll
    for (int i = 0; i < 2; i++) {
        #pragma unroll
        for (int h = 0; h < 2; h++) {
            int gi  = row0 + wm * 32 + i * 16 + h * 8 + g;
            int lab = labels[gi];
            float sum = 0.0f;
            #pragma unroll
            for (int j = 0; j < 4; j++) {
                float l0 = acc[i][j][2 * h];
                float l1 = acc[i][j][2 * h + 1];
                sum += fexp2(l0 * LOG2E) + fexp2(l1 * LOG2E);
                int gj = col0 + wn * 32 + j * 8 + 2 * t;
                if (gj == lab)     g_labval[gi] = l0;
                if (gj + 1 == lab) g_labval[gi] = l1;
            }
            sum += __shfl_xor_sync(0xffffffffu, sum, 1);
            sum += __shfl_xor_sync(0xffffffffu, sum, 2);
            if (t == 0) atomicAdd(&g_sumexp[gi], sum);
        }
    }
}

// ---------------------------------------------------------------------------
// 3) Finalize: trivial per-row combine -> mean (4096 threads)
// ---------------------------------------------------------------------------
__global__ void finalize_kernel(float* __restrict__ out) {
    int row  = blockIdx.x * blockDim.x + threadIdx.x;
    int lane = threadIdx.x & 31;
    float loss = 0.0f;
    if (row < NROW) {
        float loss2 = logf(g_sumexp[row]) - g_labval[row];
        float loss1 = logf((g_rowsum[row] - 7.3890560989306495f) / g_pos[row]); // diag=e^2
        loss = (loss1 + loss2) * (1.0f / NROW);
    }
    #pragma unroll
    for (int o = 16; o; o >>= 1) loss += __shfl_xor_sync(0xffffffffu, loss, o);
    if (lane == 0) atomicAdd(out, loss);
}

// ---------------------------------------------------------------------------
extern "C" void kernel_launch(void* const* d_in, const int* in_sizes, int n_in,
                              void* d_out, int out_size) {
    const float* st_i  = (const float*)d_in[0];
    const float* st_j  = (const float*)d_in[1];
    const float* car_i = (const float*)d_in[2];
    const float* car_j = (const float*)d_in[3];
    const float* pl_i  = (const float*)d_in[4];
    const float* pl_j  = (const float*)d_in[5];
    const int*   lab   = (const int*)d_in[6];
    const float* cst   = (const float*)d_in[7];
    const float* ccar  = (const float*)d_in[8];
    const float* cpl   = (const float*)d_in[9];
    const float* conc  = (const float*)d_in[10];
    float* out = (float*)d_out;

    prep_kernel<<<1536 + 768, 256>>>(st_i, st_j, car_i, car_j, pl_i, pl_j,
                                     cst, ccar, cpl, conc, out, out_size);

    sims_f16<<<528, 256>>>();                  // triangular grid

    dim3 gp(NC / 128, NROW / 64);              // 4 x 64 = 256 CTAs
    proto_f16<<<gp, 256>>>(lab);

    finalize_kernel<<<NROW / 256, 256>>>(out);
}